// round 6
// baseline (speedup 1.0000x reference)
#include <cuda_runtime.h>
#include <cuda_bf16.h>
#include <cstdint>
#include <math.h>

// ---------------------------------------------------------------------------
// Problem constants
#define BB 2048
#define NN 50000
#define CC 768
#define TK 16
#define NCAND 64
#define NPARTS 37
#define NT 11                 // 128-col tiles per part
#define PSPAN (NT*128)        // 1408
#define NPAD (NPARTS*PSPAN)   // 52096
#define NLISTS NPARTS         // 37 partial lists per row (merged in-CTA)
#define NEG_INF __int_as_float(0xff800000)

#define SX_SCALE 24.0f
#define SE_SCALE 480.0f

// Scratch (device globals: no cudaMalloc allowed)
__device__ int8_t g_Ei8[(size_t)NPAD * CC];   // row-normalized, scaled by SE
__device__ int8_t g_Xi8[(size_t)BB * CC];     // scaled by SX
__device__ float  g_pvals[(size_t)BB * NLISTS * TK];
__device__ int    g_pidx [(size_t)BB * NLISTS * TK];
__device__ int    g_cand [(size_t)BB * NCAND];
__device__ double g_csim [(size_t)BB * NCAND];
__device__ int    g_fidx [(size_t)BB * TK];

// ---------------------------------------------------------------------------
// Baseline-PTX helpers (NO sm_103a-gated instructions)
// ---------------------------------------------------------------------------
__device__ __forceinline__ uint32_t smem_u32(const void* p) {
    uint32_t a;
    asm("{ .reg .u64 t; cvta.to.shared.u64 t, %1; cvt.u32.u64 %0, t; }" : "=r"(a) : "l"(p));
    return a;
}
__device__ __forceinline__ void cp16(uint32_t saddr, const void* g) {
    asm volatile("cp.async.cg.shared.global [%0], [%1], 16;" :: "r"(saddr), "l"(g));
}
#define CP_COMMIT() asm volatile("cp.async.commit_group;" ::: "memory")
#define CP_WAIT2()  asm volatile("cp.async.wait_group 2;" ::: "memory")

__device__ __forceinline__ void ldm_x4(uint32_t& r0, uint32_t& r1, uint32_t& r2,
                                       uint32_t& r3, uint32_t a) {
    asm volatile("ldmatrix.sync.aligned.m8n8.x4.shared.b16 {%0,%1,%2,%3}, [%4];"
                 : "=r"(r0), "=r"(r1), "=r"(r2), "=r"(r3) : "r"(a));
}
// int8 MMA: m16n8k32, s32 accumulate (exact)
__device__ __forceinline__ void mma16832(int* c, const uint32_t* a, const uint32_t* b) {
    asm volatile(
        "mma.sync.aligned.m16n8k32.row.col.s32.s8.s8.s32 "
        "{%0,%1,%2,%3}, {%4,%5,%6,%7}, {%8,%9}, {%0,%1,%2,%3};"
        : "+r"(c[0]), "+r"(c[1]), "+r"(c[2]), "+r"(c[3])
        : "r"(a[0]), "r"(a[1]), "r"(a[2]), "r"(a[3]), "r"(b[0]), "r"(b[1]));
}
__device__ __forceinline__ uint32_t swz(uint32_t off) { return off ^ ((off >> 3) & 0x70); }

__device__ __forceinline__ uint32_t pack_q4(float a, float b, float c, float d, float s) {
    int qa = __float2int_rn(fminf(fmaxf(a * s, -127.f), 127.f));
    int qb = __float2int_rn(fminf(fmaxf(b * s, -127.f), 127.f));
    int qc = __float2int_rn(fminf(fmaxf(c * s, -127.f), 127.f));
    int qd = __float2int_rn(fminf(fmaxf(d * s, -127.f), 127.f));
    return (qa & 0xFF) | ((qb & 0xFF) << 8) | ((qc & 0xFF) << 16) | ((qd & 0xFF) << 24);
}

// ---------------------------------------------------------------------------
// Prepass: E -> int8 (row-normalized * SE); X -> int8 (* SX)
// ---------------------------------------------------------------------------
__global__ void prepE_kernel(const float* __restrict__ E) {
    int w = (blockIdx.x * blockDim.x + threadIdx.x) >> 5;
    int lane = threadIdx.x & 31;
    if (w >= NPAD) return;
    uint32_t* orow = reinterpret_cast<uint32_t*>(g_Ei8 + (size_t)w * CC);
    if (w >= NN) {
        #pragma unroll
        for (int i = 0; i < 6; i++) orow[lane + 32 * i] = 0u;
        return;
    }
    const float4* r4 = reinterpret_cast<const float4*>(E + (size_t)w * CC);
    float s = 0.f;
    float4 v[6];
    #pragma unroll
    for (int i = 0; i < 6; i++) {
        v[i] = r4[lane + 32*i];
        s += v[i].x*v[i].x + v[i].y*v[i].y + v[i].z*v[i].z + v[i].w*v[i].w;
    }
    #pragma unroll
    for (int o = 16; o; o >>= 1) s += __shfl_xor_sync(0xffffffffu, s, o);
    float inv = rsqrtf(s) * SE_SCALE;
    #pragma unroll
    for (int i = 0; i < 6; i++)
        orow[lane + 32 * i] = pack_q4(v[i].x, v[i].y, v[i].z, v[i].w, inv);
}

__global__ void prepX_kernel(const float* __restrict__ X) {
    int w = (blockIdx.x * blockDim.x + threadIdx.x) >> 5;
    int lane = threadIdx.x & 31;
    if (w >= BB) return;
    const float4* r4 = reinterpret_cast<const float4*>(X + (size_t)w * CC);
    uint32_t* orow = reinterpret_cast<uint32_t*>(g_Xi8 + (size_t)w * CC);
    #pragma unroll
    for (int i = 0; i < 6; i++) {
        float4 v = r4[lane + 32*i];
        orow[lane + 32 * i] = pack_q4(v.x, v.y, v.z, v.w, SX_SCALE);
    }
}

// ---------------------------------------------------------------------------
// Kernel 1: int8 IMMA GEMM (mma.sync m16n8k32) + streaming per-row top-16.
// 128x128 CTA tile, 8 warps (2M x 4N), warp tile 64x32, K-chunk 128 bytes.
// 4-stage cp.async ring (3 in flight), one syncthreads per chunk.
// grid(16 Mblk, 37 parts), 256 threads.
// ---------------------------------------------------------------------------
#define NSTAGE      4
#define STAGE_BYTES 32768              // A 16KB + B 16KB (128 rows x 128B each)
#define SC_OFF      (NSTAGE*STAGE_BYTES)   // 131072
#define SC_PITCH    133
#define GSMEM       (SC_OFF + 128*SC_PITCH*4)   // 199,168 B

__global__ void __launch_bounds__(256, 1) gemm_topk_kernel() {
    extern __shared__ char sm[];
    const uint32_t smb = smem_u32(sm);
    float* scores = reinterpret_cast<float*>(sm + SC_OFF);

    const int tid  = threadIdx.x;
    const int warp = tid >> 5;
    const int lane = tid & 31;
    const int m0   = blockIdx.x * 128;
    const int part = blockIdx.y;
    const int pbase = part * PSPAN;

    const int wm = warp & 1;        // 2 M-warps (64 rows each)
    const int wn = warp >> 1;       // 4 N-warps (32 cols each)

    const int NCHUNK = NT * 6;      // 66 chunks of k=128 bytes

    // issue one 32KB stage (A chunk + B chunk) via cp.async; always commits
    auto issue = [&](int ci) {
        if (ci < NCHUNK) {
            const int t = ci / 6, c = ci % 6;
            const uint32_t as = smb + (ci & (NSTAGE - 1)) * STAGE_BYTES;
            const uint32_t bs = as + 16384;
            const int8_t* Ab = g_Xi8 + (size_t)m0 * CC + c * 128;
            const int8_t* Bb = g_Ei8 + (size_t)(pbase + t * 128) * CC + c * 128;
            #pragma unroll
            for (int s = 0; s < 4; s++) {
                int u = tid + 256 * s;          // 0..1023
                int row = u >> 3, seg = u & 7;
                cp16(as + swz(row * 128 + seg * 16), Ab + (size_t)row * CC + seg * 16);
                cp16(bs + swz(row * 128 + seg * 16), Bb + (size_t)row * CC + seg * 16);
            }
        }
        CP_COMMIT();   // empty group during drain keeps wait_group counting valid
    };

    // per-(row,half) streaming top-16 (thread tid: row=tid&127, half=tid>>7)
    float tvv[TK]; int tii[TK];
    #pragma unroll
    for (int q = 0; q < TK; q++) { tvv[q] = NEG_INF; tii[q] = 0x7fffffff; }
    float mv = NEG_INF; int mp = 0;

    int acc[4][4][4];
    #pragma unroll
    for (int i = 0; i < 4; i++)
        #pragma unroll
        for (int j = 0; j < 4; j++)
            #pragma unroll
            for (int r = 0; r < 4; r++) acc[i][j][r] = 0;

    // ldmatrix lane-address components (byte layout identical to bf16 k16 case)
    const int a_row = (lane & 15);
    const int a_kh  = (lane >> 4) & 1;
    const int b_nrw = ((lane >> 4) & 1) * 8 + (lane & 7);
    const int b_kh  = (lane >> 3) & 1;

    issue(0); issue(1); issue(2);

    for (int ci = 0; ci < NCHUNK; ci++) {
        CP_WAIT2();          // chunk ci resident (<=2 younger groups outstanding)
        __syncthreads();     // all warps see stage data; all done with ci-1's stage
        issue(ci + 3);       // safe: overwrites stage of chunk ci-1

        // compute chunk ci from stage ci % 4 : 4 k-steps of k=32 bytes
        {
            const uint32_t as = smb + (ci & (NSTAGE - 1)) * STAGE_BYTES;
            const uint32_t bs = as + 16384;
            #pragma unroll
            for (int ks = 0; ks < 4; ks++) {
                uint32_t a[4][4], b[2][4];
                #pragma unroll
                for (int i = 0; i < 4; i++) {
                    uint32_t off = (uint32_t)(wm * 64 + i * 16 + a_row) * 128
                                 + ks * 32 + a_kh * 16;
                    ldm_x4(a[i][0], a[i][1], a[i][2], a[i][3], as + swz(off));
                }
                #pragma unroll
                for (int j16 = 0; j16 < 2; j16++) {
                    uint32_t off = (uint32_t)(wn * 32 + j16 * 16 + b_nrw) * 128
                                 + ks * 32 + b_kh * 16;
                    ldm_x4(b[j16][0], b[j16][1], b[j16][2], b[j16][3], bs + swz(off));
                }
                #pragma unroll
                for (int i = 0; i < 4; i++)
                    #pragma unroll
                    for (int j2 = 0; j2 < 4; j2++)
                        mma16832(acc[i][j2], a[i], &b[j2 >> 1][(j2 & 1) * 2]);
            }
        }

        if ((ci % 6) == 5) {
            // tile epilogue: stage scores ((float)s32 is exact, |acc|<2^24) then scan
            const int t = ci / 6;
            const int n0 = pbase + t * 128;
            __syncthreads();   // previous scan fully done (scores region reuse)
            #pragma unroll
            for (int i = 0; i < 4; i++) {
                int row = wm * 64 + i * 16 + (lane >> 2);
                #pragma unroll
                for (int j2 = 0; j2 < 4; j2++) {
                    int col = wn * 32 + j2 * 8 + (lane & 3) * 2;
                    scores[row * SC_PITCH + col]           = (float)acc[i][j2][0];
                    scores[row * SC_PITCH + col + 1]       = (float)acc[i][j2][1];
                    scores[(row + 8) * SC_PITCH + col]     = (float)acc[i][j2][2];
                    scores[(row + 8) * SC_PITCH + col + 1] = (float)acc[i][j2][3];
                    acc[i][j2][0] = 0; acc[i][j2][1] = 0;
                    acc[i][j2][2] = 0; acc[i][j2][3] = 0;
                }
            }
            __syncthreads();
            {
                const int r    = tid & 127;
                const int half = tid >> 7;
                const float* srow = scores + r * SC_PITCH + half * 64;
                for (int c2 = 0; c2 < 64; c2++) {
                    int n = n0 + half * 64 + c2;
                    float s = srow[c2];
                    if (n < NN && s > mv) {
                        #pragma unroll
                        for (int q = 0; q < TK; q++)
                            if (q == mp) { tvv[q] = s; tii[q] = n; }
                        mv = tvv[0]; mp = 0; int mi = tii[0];
                        #pragma unroll
                        for (int q = 1; q < TK; q++) {
                            if (tvv[q] < mv || (tvv[q] == mv && tii[q] > mi)) {
                                mv = tvv[q]; mp = q; mi = tii[q];
                            }
                        }
                    }
                }
            }
        }
    }

    // in-CTA merge of the two half-lists per row -> one sorted top-16 per part
    __syncthreads();
    float* fv = scores;                     // [256][16] values
    int*   fi = (int*)(scores + 4096);      // [256][16] indices
    {
        const int slot = ((tid >> 7) * 128 + (tid & 127)) * 16;
        #pragma unroll
        for (int q = 0; q < TK; q++) { fv[slot + q] = tvv[q]; fi[slot + q] = tii[q]; }
    }
    __syncthreads();
    if (tid < 128) {
        const int b0 = tid * 16;
        const int b1 = (128 + tid) * 16;
        const size_t base = ((size_t)(m0 + tid) * NLISTS + part) * TK;
        for (int rnd = 0; rnd < TK; rnd++) {
            float bv = NEG_INF; int bi = 0x7fffffff; int bslot = -1;
            #pragma unroll
            for (int q = 0; q < TK; q++) {
                float v0 = fv[b0 + q]; int i0 = fi[b0 + q];
                if (v0 > bv || (v0 == bv && i0 < bi)) { bv = v0; bi = i0; bslot = b0 + q; }
                float v1 = fv[b1 + q]; int i1 = fi[b1 + q];
                if (v1 > bv || (v1 == bv && i1 < bi)) { bv = v1; bi = i1; bslot = b1 + q; }
            }
            if (bslot >= 0) { fv[bslot] = NEG_INF; fi[bslot] = 0x7fffffff; }
            g_pvals[base + rnd] = bv;
            g_pidx [base + rnd] = bi;
        }
    }
}

// ---------------------------------------------------------------------------
// Kernel 2: merge 37x16 partials -> top-64 candidate pool per row (warp/row)
// ---------------------------------------------------------------------------
__global__ void merge_kernel() {
    const int warp = threadIdx.x >> 5;
    const int lane = threadIdx.x & 31;
    const int row  = blockIdx.x * 8 + warp;
    if (row >= BB) return;

    const int NC = NLISTS * TK;     // 592
    const int T = (NC + 31) / 32;   // 19
    float lv[T]; int li[T];
    #pragma unroll
    for (int t = 0; t < T; t++) {
        int g = lane + t * 32;
        if (g < NC) {
            lv[t] = g_pvals[(size_t)row * NC + g];
            li[t] = g_pidx [(size_t)row * NC + g];
        } else { lv[t] = NEG_INF; li[t] = 0x7fffffff; }
    }
    for (int rnd = 0; rnd < NCAND; rnd++) {
        float bv = NEG_INF; int bi = 0x7fffffff; int bs = -1;
        #pragma unroll
        for (int t = 0; t < T; t++)
            if (lv[t] > bv || (lv[t] == bv && li[t] < bi)) { bv = lv[t]; bi = li[t]; bs = t; }
        float wv = bv; int wi = bi;
        #pragma unroll
        for (int o = 16; o; o >>= 1) {
            float ov = __shfl_xor_sync(0xffffffffu, wv, o);
            int   oi = __shfl_xor_sync(0xffffffffu, wi, o);
            if (ov > wv || (ov == wv && oi < wi)) { wv = ov; wi = oi; }
        }
        if (bs >= 0 && bv == wv && bi == wi) { lv[bs] = NEG_INF; li[bs] = 0x7fffffff; }
        if (lane == 0) g_cand[row * NCAND + rnd] = wi;
    }
}

// ---------------------------------------------------------------------------
// Kernel 2.5a: fp64 exact sims — one WARP per (row, candidate)
// ---------------------------------------------------------------------------
__global__ void refine_dot_kernel(const float* __restrict__ X, const float* __restrict__ E) {
    const int gw   = blockIdx.x * 8 + (threadIdx.x >> 5);
    const int lane = threadIdx.x & 31;
    const int row  = gw >> 6;
    const int slot = gw & 63;
    if (row >= BB) return;
    const int cand = g_cand[row * NCAND + slot];
    const float4* x4 = reinterpret_cast<const float4*>(X + (size_t)row  * CC);
    const float4* e4 = reinterpret_cast<const float4*>(E + (size_t)cand * CC);

    double dot = 0.0, e2 = 0.0;
    #pragma unroll
    for (int i = 0; i < 6; i++) {
        float4 xv = x4[lane + 32 * i];
        float4 ev = e4[lane + 32 * i];
        dot = fma((double)xv.x, (double)ev.x, dot);
        e2  = fma((double)ev.x, (double)ev.x, e2);
        dot = fma((double)xv.y, (double)ev.y, dot);
        e2  = fma((double)ev.y, (double)ev.y, e2);
        dot = fma((double)xv.z, (double)ev.z, dot);
        e2  = fma((double)ev.z, (double)ev.z, e2);
        dot = fma((double)xv.w, (double)ev.w, dot);
        e2  = fma((double)ev.w, (double)ev.w, e2);
    }
    #pragma unroll
    for (int o = 16; o; o >>= 1) {
        dot += __shfl_xor_sync(0xffffffffu, dot, o);
        e2  += __shfl_xor_sync(0xffffffffu, e2,  o);
    }
    if (lane == 0) g_csim[row * NCAND + slot] = dot / sqrt(e2);
}

// Kernel 2.5b: sorted top-16 of the 64 exact sims (warp per row, 2 per lane)
__global__ void refine_select_kernel() {
    const int warp = threadIdx.x >> 5;
    const int lane = threadIdx.x & 31;
    const int row  = blockIdx.x * 8 + warp;
    if (row >= BB) return;

    double v[2]; int idx[2];
    #pragma unroll
    for (int j = 0; j < 2; j++) {
        v[j]   = g_csim[row * NCAND + lane + 32 * j];
        idx[j] = g_cand[row * NCAND + lane + 32 * j];
    }
    for (int rnd = 0; rnd < TK; rnd++) {
        double bv; int bi;
        if (v[0] > v[1] || (v[0] == v[1] && idx[0] < idx[1])) { bv = v[0]; bi = idx[0]; }
        else                                                   { bv = v[1]; bi = idx[1]; }
        double wv = bv; int wi = bi;
        #pragma unroll
        for (int o = 16; o; o >>= 1) {
            double ov = __shfl_xor_sync(0xffffffffu, wv, o);
            int    oi = __shfl_xor_sync(0xffffffffu, wi, o);
            if (ov > wv || (ov == wv && oi < wi)) { wv = ov; wi = oi; }
        }
        if (idx[0] == wi)      { v[0] = -INFINITY; idx[0] = 0x7fffffff; }
        else if (idx[1] == wi) { v[1] = -INFINITY; idx[1] = 0x7fffffff; }
        if (lane == 0) g_fidx[row * TK + rnd] = wi;
    }
}

// ---------------------------------------------------------------------------
// Kernel 3: gather with reference's reshape(-1,B,C).transpose(1,0,2) scramble
// ---------------------------------------------------------------------------
__global__ void gather_kernel(const float* __restrict__ E, float* __restrict__ out) {
    const int bj = blockIdx.x;        // b*16 + j
    const int b = bj >> 4, j = bj & 15;
    const int src_row  = j * (BB / TK) + (b >> 4);
    const int src_slot = b & 15;
    const int src = g_fidx[src_row * TK + src_slot];
    const float4* s4 = reinterpret_cast<const float4*>(E + (size_t)src * CC);
    float4* d4 = reinterpret_cast<float4*>(out + (size_t)bj * CC);
    d4[threadIdx.x] = s4[threadIdx.x];
}

// ---------------------------------------------------------------------------
extern "C" void kernel_launch(void* const* d_in, const int* in_sizes, int n_in,
                              void* d_out, int out_size) {
    const float* X = (const float*)d_in[0];
    const float* E = (const float*)d_in[1];
    float* out = (float*)d_out;
    (void)in_sizes; (void)n_in; (void)out_size;

    cudaFuncSetAttribute(gemm_topk_kernel,
                         cudaFuncAttributeMaxDynamicSharedMemorySize, GSMEM);

    prepE_kernel<<<NPAD / 8, 256>>>(E);
    prepX_kernel<<<BB / 8, 256>>>(X);
    gemm_topk_kernel<<<dim3(16, NPARTS), 256, GSMEM>>>();
    merge_kernel<<<BB / 8, 256>>>();
    refine_dot_kernel<<<BB * NCAND / 8, 256>>>(X, E);
    refine_select_kernel<<<BB / 8, 256>>>();
    gather_kernel<<<BB * TK, 192>>>(E, out);
}

// round 7
// speedup vs baseline: 1.7855x; 1.7855x over previous
#include <cuda_runtime.h>
#include <cuda_bf16.h>
#include <cstdint>
#include <math.h>

// ---------------------------------------------------------------------------
// Problem constants
#define BB 2048
#define NN 50000
#define CC 768
#define TK 16
#define NCAND 32
#define NPARTS 37
#define NT 11                 // 128-col tiles per part
#define PSPAN (NT*128)        // 1408
#define NPAD (NPARTS*PSPAN)   // 52096
#define NLISTS (2*NPARTS)     // 74 partial lists per row (2 col-halves per part)
#define NEG_INF __int_as_float(0xff800000)

// Scratch (device globals: no cudaMalloc allowed)
__device__ __nv_bfloat16 g_Ebf[(size_t)NPAD * CC];   // row-scaled by 1/||e||
__device__ __nv_bfloat16 g_Xbf[(size_t)BB * CC];
__device__ float  g_pvals[(size_t)BB * NLISTS * TK];
__device__ int    g_pidx [(size_t)BB * NLISTS * TK];
__device__ int    g_cand [(size_t)BB * NCAND];
__device__ double g_csim [(size_t)BB * NCAND];
__device__ int    g_fidx [(size_t)BB * TK];

// ---------------------------------------------------------------------------
// Baseline-PTX helpers (NO sm_103a-gated instructions)
// ---------------------------------------------------------------------------
__device__ __forceinline__ uint32_t smem_u32(const void* p) {
    uint32_t a;
    asm("{ .reg .u64 t; cvta.to.shared.u64 t, %1; cvt.u32.u64 %0, t; }" : "=r"(a) : "l"(p));
    return a;
}
__device__ __forceinline__ void cp16(uint32_t saddr, const void* g) {
    asm volatile("cp.async.cg.shared.global [%0], [%1], 16;" :: "r"(saddr), "l"(g));
}
#define CP_COMMIT() asm volatile("cp.async.commit_group;" ::: "memory")
#define CP_WAIT0()  asm volatile("cp.async.wait_group 0;" ::: "memory")
#define CP_WAIT1()  asm volatile("cp.async.wait_group 1;" ::: "memory")

__device__ __forceinline__ void ldm_x4(uint32_t& r0, uint32_t& r1, uint32_t& r2,
                                       uint32_t& r3, uint32_t a) {
    asm volatile("ldmatrix.sync.aligned.m8n8.x4.shared.b16 {%0,%1,%2,%3}, [%4];"
                 : "=r"(r0), "=r"(r1), "=r"(r2), "=r"(r3) : "r"(a));
}
__device__ __forceinline__ void mma16816(float* c, const uint32_t* a, const uint32_t* b) {
    asm volatile(
        "mma.sync.aligned.m16n8k16.row.col.f32.bf16.bf16.f32 "
        "{%0,%1,%2,%3}, {%4,%5,%6,%7}, {%8,%9}, {%0,%1,%2,%3};"
        : "+f"(c[0]), "+f"(c[1]), "+f"(c[2]), "+f"(c[3])
        : "r"(a[0]), "r"(a[1]), "r"(a[2]), "r"(a[3]), "r"(b[0]), "r"(b[1]));
}
__device__ __forceinline__ uint32_t swz(uint32_t off) { return off ^ ((off >> 3) & 0x70); }

// ---------------------------------------------------------------------------
// Prepass: E -> bf16 scaled by 1/||e|| (rows >= NN zeroed); X -> bf16
// ---------------------------------------------------------------------------
__global__ void prepE_kernel(const float* __restrict__ E) {
    int w = (blockIdx.x * blockDim.x + threadIdx.x) >> 5;
    int lane = threadIdx.x & 31;
    if (w >= NPAD) return;
    uint32_t* orow = reinterpret_cast<uint32_t*>(g_Ebf + (size_t)w * CC);
    if (w >= NN) {
        #pragma unroll
        for (int i = 0; i < 6; i++) { orow[(lane+32*i)*2] = 0u; orow[(lane+32*i)*2+1] = 0u; }
        return;
    }
    const float4* r4 = reinterpret_cast<const float4*>(E + (size_t)w * CC);
    float s = 0.f;
    float4 v[6];
    #pragma unroll
    for (int i = 0; i < 6; i++) {
        v[i] = r4[lane + 32*i];
        s += v[i].x*v[i].x + v[i].y*v[i].y + v[i].z*v[i].z + v[i].w*v[i].w;
    }
    #pragma unroll
    for (int o = 16; o; o >>= 1) s += __shfl_xor_sync(0xffffffffu, s, o);
    float inv = rsqrtf(s);
    #pragma unroll
    for (int i = 0; i < 6; i++) {
        __nv_bfloat162 h0 = __floats2bfloat162_rn(v[i].x*inv, v[i].y*inv);
        __nv_bfloat162 h1 = __floats2bfloat162_rn(v[i].z*inv, v[i].w*inv);
        orow[(lane+32*i)*2]   = *reinterpret_cast<uint32_t*>(&h0);
        orow[(lane+32*i)*2+1] = *reinterpret_cast<uint32_t*>(&h1);
    }
}

__global__ void prepX_kernel(const float* __restrict__ X) {
    int w = (blockIdx.x * blockDim.x + threadIdx.x) >> 5;
    int lane = threadIdx.x & 31;
    if (w >= BB) return;
    const float4* r4 = reinterpret_cast<const float4*>(X + (size_t)w * CC);
    uint32_t* orow = reinterpret_cast<uint32_t*>(g_Xbf + (size_t)w * CC);
    #pragma unroll
    for (int i = 0; i < 6; i++) {
        float4 v = r4[lane + 32*i];
        __nv_bfloat162 h0 = __floats2bfloat162_rn(v.x, v.y);
        __nv_bfloat162 h1 = __floats2bfloat162_rn(v.z, v.w);
        orow[(lane+32*i)*2]   = *reinterpret_cast<uint32_t*>(&h0);
        orow[(lane+32*i)*2+1] = *reinterpret_cast<uint32_t*>(&h1);
    }
}

// Dummy no-op: placed as 3rd launch so ncu (which captures the 4th launch)
// profiles the GEMM kernel.
__global__ void dummy_kernel() {}

// ---------------------------------------------------------------------------
// Kernel 1: bf16 HMMA GEMM (mma.sync m16n8k16) + streaming per-row top-16.
// 128x128 CTA tile, 8 warps (2M x 4N), warp tile 64x32, K-chunk 64.
// cp.async double-buffered stages; epilogue via smem scores (pitch 133).
// grid(16 Mblk, 37 parts), 256 threads.
// ---------------------------------------------------------------------------
#define STAGE_BYTES 32768              // A 16KB + B 16KB
#define SC_OFF      65536              // scores after 2 stages
#define SC_PITCH    133
#define GSMEM       (SC_OFF + 128*SC_PITCH*4)   // 133,632 B

__global__ void __launch_bounds__(256, 1) gemm_topk_kernel() {
    extern __shared__ char sm[];
    const uint32_t smb = smem_u32(sm);
    float* scores = reinterpret_cast<float*>(sm + SC_OFF);

    const int tid  = threadIdx.x;
    const int warp = tid >> 5;
    const int lane = tid & 31;
    const int m0   = blockIdx.x * 128;
    const int part = blockIdx.y;
    const int pbase = part * PSPAN;

    const int wm = warp & 1;        // 2 M-warps (64 rows each)
    const int wn = warp >> 1;       // 4 N-warps (32 cols each)

    // issue one 32KB stage (A chunk + B chunk) via cp.async
    auto issue = [&](int ci, int stage) {
        const int t = ci / 12, c = ci % 12;
        const uint32_t as = smb + stage * STAGE_BYTES;
        const uint32_t bs = as + 16384;
        const __nv_bfloat16* Ab = g_Xbf + (size_t)m0 * CC + c * 64;
        const __nv_bfloat16* Bb = g_Ebf + (size_t)(pbase + t * 128) * CC + c * 64;
        #pragma unroll
        for (int s = 0; s < 4; s++) {
            int u = tid + 256 * s;          // 0..1023
            int row = u >> 3, seg = u & 7;
            cp16(as + swz(row * 128 + seg * 16), Ab + (size_t)row * CC + seg * 8);
            cp16(bs + swz(row * 128 + seg * 16), Bb + (size_t)row * CC + seg * 8);
        }
        CP_COMMIT();
    };

    // per-(row,half) streaming top-16 (thread tid: row=tid&127, half=tid>>7)
    float tvv[TK]; int tii[TK];
    #pragma unroll
    for (int q = 0; q < TK; q++) { tvv[q] = NEG_INF; tii[q] = 0x7fffffff; }
    float mv = NEG_INF; int mp = 0;

    float acc[4][4][4];
    #pragma unroll
    for (int i = 0; i < 4; i++)
        #pragma unroll
        for (int j = 0; j < 4; j++)
            #pragma unroll
            for (int r = 0; r < 4; r++) acc[i][j][r] = 0.f;

    // precomputed ldmatrix lane-address components
    const int a_row = (lane & 15);
    const int a_kh  = (lane >> 4) & 1;
    const int b_nrw = ((lane >> 4) & 1) * 8 + (lane & 7);
    const int b_kh  = (lane >> 3) & 1;

    issue(0, 0);

    const int NCHUNK = NT * 12;   // 132
    for (int ci = 0; ci < NCHUNK; ci++) {
        if (ci + 1 < NCHUNK) { issue(ci + 1, (ci + 1) & 1); CP_WAIT1(); }
        else                 { CP_WAIT0(); }
        __syncthreads();

        // compute chunk ci from stage ci&1
        {
            const uint32_t as = smb + (ci & 1) * STAGE_BYTES;
            const uint32_t bs = as + 16384;
            #pragma unroll
            for (int ks = 0; ks < 4; ks++) {
                uint32_t a[4][4], b[2][4];
                #pragma unroll
                for (int i = 0; i < 4; i++) {
                    uint32_t off = (uint32_t)(wm * 64 + i * 16 + a_row) * 128
                                 + ks * 32 + a_kh * 16;
                    ldm_x4(a[i][0], a[i][1], a[i][2], a[i][3], as + swz(off));
                }
                #pragma unroll
                for (int j16 = 0; j16 < 2; j16++) {
                    uint32_t off = (uint32_t)(wn * 32 + j16 * 16 + b_nrw) * 128
                                 + ks * 32 + b_kh * 16;
                    ldm_x4(b[j16][0], b[j16][1], b[j16][2], b[j16][3], bs + swz(off));
                }
                #pragma unroll
                for (int i = 0; i < 4; i++)
                    #pragma unroll
                    for (int j2 = 0; j2 < 4; j2++)
                        mma16816(acc[i][j2], a[i], &b[j2 >> 1][(j2 & 1) * 2]);
            }
        }

        if ((ci % 12) == 11) {
            // tile epilogue: stage scores then scan
            const int t = ci / 12;
            const int n0 = pbase + t * 128;
            __syncthreads();   // previous scan fully done (scores reuse)
            #pragma unroll
            for (int i = 0; i < 4; i++) {
                int row = wm * 64 + i * 16 + (lane >> 2);
                #pragma unroll
                for (int j2 = 0; j2 < 4; j2++) {
                    int col = wn * 32 + j2 * 8 + (lane & 3) * 2;
                    scores[row * SC_PITCH + col]           = acc[i][j2][0];
                    scores[row * SC_PITCH + col + 1]       = acc[i][j2][1];
                    scores[(row + 8) * SC_PITCH + col]     = acc[i][j2][2];
                    scores[(row + 8) * SC_PITCH + col + 1] = acc[i][j2][3];
                    acc[i][j2][0] = 0.f; acc[i][j2][1] = 0.f;
                    acc[i][j2][2] = 0.f; acc[i][j2][3] = 0.f;
                }
            }
            __syncthreads();
            {
                const int r    = tid & 127;
                const int half = tid >> 7;
                const int cbase = n0 + half * 64;
                // number of valid columns in this 64-wide half (tail guard)
                int nv = NN - cbase;
                nv = nv < 0 ? 0 : (nv > 64 ? 64 : nv);
                const float* srow = scores + r * SC_PITCH + half * 64;
                int c2 = 0;
                for (; c2 + 4 <= nv; c2 += 4) {
                    float s0 = srow[c2], s1 = srow[c2+1], s2 = srow[c2+2], s3 = srow[c2+3];
                    float mx = fmaxf(fmaxf(s0, s1), fmaxf(s2, s3));
                    if (mx > mv) {
                        #pragma unroll
                        for (int u = 0; u < 4; u++) {
                            float s = (u == 0) ? s0 : (u == 1) ? s1 : (u == 2) ? s2 : s3;
                            if (s > mv) {
                                #pragma unroll
                                for (int q = 0; q < TK; q++)
                                    if (q == mp) { tvv[q] = s; tii[q] = cbase + c2 + u; }
                                mv = tvv[0]; mp = 0; int mi = tii[0];
                                #pragma unroll
                                for (int q = 1; q < TK; q++) {
                                    if (tvv[q] < mv || (tvv[q] == mv && tii[q] > mi)) {
                                        mv = tvv[q]; mp = q; mi = tii[q];
                                    }
                                }
                            }
                        }
                    }
                }
                for (; c2 < nv; c2++) {
                    float s = srow[c2];
                    if (s > mv) {
                        #pragma unroll
                        for (int q = 0; q < TK; q++)
                            if (q == mp) { tvv[q] = s; tii[q] = cbase + c2; }
                        mv = tvv[0]; mp = 0; int mi = tii[0];
                        #pragma unroll
                        for (int q = 1; q < TK; q++) {
                            if (tvv[q] < mv || (tvv[q] == mv && tii[q] > mi)) {
                                mv = tvv[q]; mp = q; mi = tii[q];
                            }
                        }
                    }
                }
            }
        }
        __syncthreads();   // stage buffer safe to overwrite next iteration
    }

    // dump candidate lists: list id = part*2 + half
    {
        const int b = m0 + (tid & 127);
        const int list = part * 2 + (tid >> 7);
        const size_t base = ((size_t)b * NLISTS + list) * TK;
        #pragma unroll
        for (int q = 0; q < TK; q++) { g_pvals[base + q] = tvv[q]; g_pidx[base + q] = tii[q]; }
    }
}

// ---------------------------------------------------------------------------
// Kernel 2: merge 74x16 partials -> top-32 candidate pool per row (warp/row)
// ---------------------------------------------------------------------------
__global__ void merge_kernel() {
    const int warp = threadIdx.x >> 5;
    const int lane = threadIdx.x & 31;
    const int row  = blockIdx.x * 8 + warp;
    if (row >= BB) return;

    const int NC = NLISTS * TK;   // 1184
    const int T = NC / 32;        // 37
    float lv[T]; int li[T];
    #pragma unroll
    for (int t = 0; t < T; t++) {
        int g = lane + t * 32;
        lv[t] = g_pvals[(size_t)row * NC + g];
        li[t] = g_pidx [(size_t)row * NC + g];
    }
    for (int rnd = 0; rnd < NCAND; rnd++) {
        float bv = NEG_INF; int bi = 0x7fffffff; int bs = -1;
        #pragma unroll
        for (int t = 0; t < T; t++)
            if (lv[t] > bv || (lv[t] == bv && li[t] < bi)) { bv = lv[t]; bi = li[t]; bs = t; }
        float wv = bv; int wi = bi;
        #pragma unroll
        for (int o = 16; o; o >>= 1) {
            float ov = __shfl_xor_sync(0xffffffffu, wv, o);
            int   oi = __shfl_xor_sync(0xffffffffu, wi, o);
            if (ov > wv || (ov == wv && oi < wi)) { wv = ov; wi = oi; }
        }
        if (bs >= 0 && bv == wv && bi == wi) { lv[bs] = NEG_INF; li[bs] = 0x7fffffff; }
        if (lane == 0) g_cand[row * NCAND + rnd] = wi;
    }
}

// ---------------------------------------------------------------------------
// Kernel 2.5a: fp64 exact sims — one WARP per (row, candidate)
// ---------------------------------------------------------------------------
__global__ void refine_dot_kernel(const float* __restrict__ X, const float* __restrict__ E) {
    const int gw   = blockIdx.x * 8 + (threadIdx.x >> 5);
    const int lane = threadIdx.x & 31;
    const int row  = gw >> 5;
    const int slot = gw & 31;
    if (row >= BB) return;
    const int cand = g_cand[row * NCAND + slot];
    const float4* x4 = reinterpret_cast<const float4*>(X + (size_t)row  * CC);
    const float4* e4 = reinterpret_cast<const float4*>(E + (size_t)cand * CC);

    double dot = 0.0, e2 = 0.0;
    #pragma unroll
    for (int i = 0; i < 6; i++) {
        float4 xv = x4[lane + 32 * i];
        float4 ev = e4[lane + 32 * i];
        dot = fma((double)xv.x, (double)ev.x, dot);
        e2  = fma((double)ev.x, (double)ev.x, e2);
        dot = fma((double)xv.y, (double)ev.y, dot);
        e2  = fma((double)ev.y, (double)ev.y, e2);
        dot = fma((double)xv.z, (double)ev.z, dot);
        e2  = fma((double)ev.z, (double)ev.z, e2);
        dot = fma((double)xv.w, (double)ev.w, dot);
        e2  = fma((double)ev.w, (double)ev.w, e2);
    }
    #pragma unroll
    for (int o = 16; o; o >>= 1) {
        dot += __shfl_xor_sync(0xffffffffu, dot, o);
        e2  += __shfl_xor_sync(0xffffffffu, e2,  o);
    }
    if (lane == 0) g_csim[row * NCAND + slot] = dot / sqrt(e2);
}

// Kernel 2.5b: sorted top-16 of the 32 exact sims (warp per row)
__global__ void refine_select_kernel() {
    const int warp = threadIdx.x >> 5;
    const int lane = threadIdx.x & 31;
    const int row  = blockIdx.x * 8 + warp;
    if (row >= BB) return;

    double v = g_csim[row * NCAND + lane];
    int  idx = g_cand[row * NCAND + lane];
    for (int rnd = 0; rnd < TK; rnd++) {
        double wv = v; int wi = idx;
        #pragma unroll
        for (int o = 16; o; o >>= 1) {
            double ov = __shfl_xor_sync(0xffffffffu, wv, o);
            int    oi = __shfl_xor_sync(0xffffffffu, wi, o);
            if (ov > wv || (ov == wv && oi < wi)) { wv = ov; wi = oi; }
        }
        if (idx == wi) { v = -INFINITY; idx = 0x7fffffff; }
        if (lane == 0) g_fidx[row * TK + rnd] = wi;
    }
}

// ---------------------------------------------------------------------------
// Kernel 3: gather with reference's reshape(-1,B,C).transpose(1,0,2) scramble
// ---------------------------------------------------------------------------
__global__ void gather_kernel(const float* __restrict__ E, float* __restrict__ out) {
    const int bj = blockIdx.x;        // b*16 + j
    const int b = bj >> 4, j = bj & 15;
    const int src_row  = j * (BB / TK) + (b >> 4);
    const int src_slot = b & 15;
    const int src = g_fidx[src_row * TK + src_slot];
    const float4* s4 = reinterpret_cast<const float4*>(E + (size_t)src * CC);
    float4* d4 = reinterpret_cast<float4*>(out + (size_t)bj * CC);
    d4[threadIdx.x] = s4[threadIdx.x];
}

// ---------------------------------------------------------------------------
extern "C" void kernel_launch(void* const* d_in, const int* in_sizes, int n_in,
                              void* d_out, int out_size) {
    const float* X = (const float*)d_in[0];
    const float* E = (const float*)d_in[1];
    float* out = (float*)d_out;
    (void)in_sizes; (void)n_in; (void)out_size;

    cudaFuncSetAttribute(gemm_topk_kernel,
                         cudaFuncAttributeMaxDynamicSharedMemorySize, GSMEM);

    prepE_kernel<<<NPAD / 8, 256>>>(E);     // launch 1
    prepX_kernel<<<BB / 8, 256>>>(X);       // launch 2
    dummy_kernel<<<1, 32>>>();              // launch 3 (so gemm is 4th -> profiled)
    gemm_topk_kernel<<<dim3(16, NPARTS), 256, GSMEM>>>();   // launch 4
    merge_kernel<<<BB / 8, 256>>>();
    refine_dot_kernel<<<BB * NCAND / 8, 256>>>(X, E);
    refine_select_kernel<<<BB / 8, 256>>>();
    gather_kernel<<<BB * TK, 192>>>(E, out);
}

// round 8
// speedup vs baseline: 1.7952x; 1.0054x over previous
#include <cuda_runtime.h>
#include <cuda_bf16.h>
#include <cstdint>
#include <math.h>

// ---------------------------------------------------------------------------
// Problem constants
#define BB 2048
#define NN 50000
#define CC 768
#define TK 16
#define NCAND 32
#define NPARTS 37
#define NT 11                 // 128-col tiles per part
#define PSPAN (NT*128)        // 1408
#define NPAD (NPARTS*PSPAN)   // 52096
#define NLISTS (2*NPARTS)     // 74 partial lists per row (2 col-halves per part)
#define NEG_INF __int_as_float(0xff800000)

// Scratch (device globals: no cudaMalloc allowed)
__device__ __nv_bfloat16 g_Ebf[(size_t)NPAD * CC];   // row-scaled by 1/||e||
__device__ __nv_bfloat16 g_Xbf[(size_t)BB * CC];
__device__ float  g_pvals[(size_t)BB * NLISTS * TK];
__device__ int    g_pidx [(size_t)BB * NLISTS * TK];
__device__ int    g_cand [(size_t)BB * NCAND];
__device__ double g_csim [(size_t)BB * NCAND];
__device__ int    g_fidx [(size_t)BB * TK];

// ---------------------------------------------------------------------------
// Baseline-PTX helpers (NO sm_103a-gated instructions)
// ---------------------------------------------------------------------------
__device__ __forceinline__ uint32_t smem_u32(const void* p) {
    uint32_t a;
    asm("{ .reg .u64 t; cvta.to.shared.u64 t, %1; cvt.u32.u64 %0, t; }" : "=r"(a) : "l"(p));
    return a;
}
__device__ __forceinline__ void cp16(uint32_t saddr, const void* g) {
    asm volatile("cp.async.cg.shared.global [%0], [%1], 16;" :: "r"(saddr), "l"(g));
}
#define CP_COMMIT() asm volatile("cp.async.commit_group;" ::: "memory")
#define CP_WAIT1()  asm volatile("cp.async.wait_group 1;" ::: "memory")

__device__ __forceinline__ void ldm_x4(uint32_t& r0, uint32_t& r1, uint32_t& r2,
                                       uint32_t& r3, uint32_t a) {
    asm volatile("ldmatrix.sync.aligned.m8n8.x4.shared.b16 {%0,%1,%2,%3}, [%4];"
                 : "=r"(r0), "=r"(r1), "=r"(r2), "=r"(r3) : "r"(a));
}
__device__ __forceinline__ void mma16816(float* c, const uint32_t* a, const uint32_t* b) {
    asm volatile(
        "mma.sync.aligned.m16n8k16.row.col.f32.bf16.bf16.f32 "
        "{%0,%1,%2,%3}, {%4,%5,%6,%7}, {%8,%9}, {%0,%1,%2,%3};"
        : "+f"(c[0]), "+f"(c[1]), "+f"(c[2]), "+f"(c[3])
        : "r"(a[0]), "r"(a[1]), "r"(a[2]), "r"(a[3]), "r"(b[0]), "r"(b[1]));
}
__device__ __forceinline__ uint32_t swz(uint32_t off) { return off ^ ((off >> 3) & 0x70); }

// ---------------------------------------------------------------------------
// Prepass: E -> bf16 scaled by 1/||e|| (rows >= NN zeroed); X -> bf16
// ---------------------------------------------------------------------------
__global__ void prepE_kernel(const float* __restrict__ E) {
    int w = (blockIdx.x * blockDim.x + threadIdx.x) >> 5;
    int lane = threadIdx.x & 31;
    if (w >= NPAD) return;
    uint32_t* orow = reinterpret_cast<uint32_t*>(g_Ebf + (size_t)w * CC);
    if (w >= NN) {
        #pragma unroll
        for (int i = 0; i < 6; i++) { orow[(lane+32*i)*2] = 0u; orow[(lane+32*i)*2+1] = 0u; }
        return;
    }
    const float4* r4 = reinterpret_cast<const float4*>(E + (size_t)w * CC);
    float s = 0.f;
    float4 v[6];
    #pragma unroll
    for (int i = 0; i < 6; i++) {
        v[i] = r4[lane + 32*i];
        s += v[i].x*v[i].x + v[i].y*v[i].y + v[i].z*v[i].z + v[i].w*v[i].w;
    }
    #pragma unroll
    for (int o = 16; o; o >>= 1) s += __shfl_xor_sync(0xffffffffu, s, o);
    float inv = rsqrtf(s);
    #pragma unroll
    for (int i = 0; i < 6; i++) {
        __nv_bfloat162 h0 = __floats2bfloat162_rn(v[i].x*inv, v[i].y*inv);
        __nv_bfloat162 h1 = __floats2bfloat162_rn(v[i].z*inv, v[i].w*inv);
        orow[(lane+32*i)*2]   = *reinterpret_cast<uint32_t*>(&h0);
        orow[(lane+32*i)*2+1] = *reinterpret_cast<uint32_t*>(&h1);
    }
}

__global__ void prepX_kernel(const float* __restrict__ X) {
    int w = (blockIdx.x * blockDim.x + threadIdx.x) >> 5;
    int lane = threadIdx.x & 31;
    if (w >= BB) return;
    const float4* r4 = reinterpret_cast<const float4*>(X + (size_t)w * CC);
    uint32_t* orow = reinterpret_cast<uint32_t*>(g_Xbf + (size_t)w * CC);
    #pragma unroll
    for (int i = 0; i < 6; i++) {
        float4 v = r4[lane + 32*i];
        __nv_bfloat162 h0 = __floats2bfloat162_rn(v.x, v.y);
        __nv_bfloat162 h1 = __floats2bfloat162_rn(v.z, v.w);
        orow[(lane+32*i)*2]   = *reinterpret_cast<uint32_t*>(&h0);
        orow[(lane+32*i)*2+1] = *reinterpret_cast<uint32_t*>(&h1);
    }
}

// Dummy no-op: placed as 3rd launch so ncu (which captures the 4th launch)
// profiles the GEMM kernel.
__global__ void dummy_kernel() {}

// ---------------------------------------------------------------------------
// Kernel 1: bf16 HMMA GEMM (mma.sync m16n8k16) + streaming per-row top-16.
// 128x128 CTA tile, 8 warps (2M x 4N), warp tile 64x32, K-chunk 64.
// 3-stage cp.async ring, issue distance 2, ONE syncthreads per chunk.
// All per-thread address components hoisted out of the main loop.
// grid(16 Mblk, 37 parts), 256 threads.
// ---------------------------------------------------------------------------
#define NSTAGE      3
#define STAGE_BYTES 32768              // A 16KB + B 16KB
#define SC_OFF      (NSTAGE*STAGE_BYTES)   // 98304
#define SC_PITCH    133
#define GSMEM       (SC_OFF + 128*SC_PITCH*4)   // 166,400 B

__global__ void __launch_bounds__(256, 1) gemm_topk_kernel() {
    extern __shared__ char sm[];
    const uint32_t smb = smem_u32(sm);
    float* scores = reinterpret_cast<float*>(sm + SC_OFF);

    const int tid  = threadIdx.x;
    const int warp = tid >> 5;
    const int lane = tid & 31;
    const int m0   = blockIdx.x * 128;
    const int part = blockIdx.y;
    const int pbase = part * PSPAN;

    const int wm = warp & 1;        // 2 M-warps (64 rows each)
    const int wn = warp >> 1;       // 4 N-warps (32 cols each)

    const int NCHUNK = NT * 12;     // 132

    // ---- hoisted cp.async per-thread address components
    const int cp_seg = tid & 7;                 // constant across s
    uint32_t cp_sw[4];                          // swizzled smem offsets
    uint32_t cp_el[4];                          // global element offsets
    #pragma unroll
    for (int s = 0; s < 4; s++) {
        int row = (tid >> 3) + 32 * s;
        cp_sw[s] = (uint32_t)row * 128 + ((uint32_t)(cp_seg * 16) ^ (((uint32_t)row & 7) << 4));
        cp_el[s] = (uint32_t)row * CC + cp_seg * 8;
    }

    // ---- hoisted ldmatrix address components
    // swz(R + v) = R + (v ^ mask), mask = (row & 7) << 4 (row-constant per thread)
    const int a_row = (lane & 15);
    const int a_kh  = (lane >> 4) & 1;
    const int b_nrw = ((lane >> 4) & 1) * 8 + (lane & 7);
    const int b_kh  = (lane >> 3) & 1;
    const uint32_t RA = (uint32_t)(wm * 64 + a_row) * 128;        // + i*2048
    const uint32_t RB = (uint32_t)(wn * 32 + b_nrw) * 128;        // + j16*2048
    const uint32_t xbaseA = ((uint32_t)(a_kh * 16)) ^ (((uint32_t)a_row & 7) << 4);
    const uint32_t xbaseB = ((uint32_t)(b_kh * 16)) ^ (((uint32_t)b_nrw & 7) << 4);

    // issue one 32KB stage (A chunk + B chunk) via cp.async; always commits
    auto issue = [&](int ci) {
        if (ci < NCHUNK) {
            const int t = ci / 12, c = ci - t * 12;
            const uint32_t as = smb + (ci % NSTAGE) * STAGE_BYTES;
            const uint32_t bs = as + 16384;
            const __nv_bfloat16* Ab = g_Xbf + (size_t)m0 * CC + c * 64;
            const __nv_bfloat16* Bb = g_Ebf + (size_t)(pbase + t * 128) * CC + c * 64;
            #pragma unroll
            for (int s = 0; s < 4; s++) {
                cp16(as + cp_sw[s], Ab + cp_el[s]);
                cp16(bs + cp_sw[s], Bb + cp_el[s]);
            }
        }
        CP_COMMIT();   // empty group during drain keeps wait_group counting valid
    };

    // per-(row,half) streaming top-16 (thread tid: row=tid&127, half=tid>>7)
    float tvv[TK]; int tii[TK];
    #pragma unroll
    for (int q = 0; q < TK; q++) { tvv[q] = NEG_INF; tii[q] = 0x7fffffff; }
    float mv = NEG_INF; int mp = 0;

    float acc[4][4][4];
    #pragma unroll
    for (int i = 0; i < 4; i++)
        #pragma unroll
        for (int j = 0; j < 4; j++)
            #pragma unroll
            for (int r = 0; r < 4; r++) acc[i][j][r] = 0.f;

    issue(0); issue(1);

    for (int ci = 0; ci < NCHUNK; ci++) {
        CP_WAIT1();          // groups 0..ci complete (<=1 younger outstanding)
        __syncthreads();     // data visible; all warps done computing ci-1
        issue(ci + 2);       // overwrites stage of ci-1: safe after the barrier

        // compute chunk ci from stage ci % 3
        {
            const uint32_t as = smb + (ci % NSTAGE) * STAGE_BYTES;
            const uint32_t aBase = as + RA;
            const uint32_t bBase = as + 16384 + RB;
            #pragma unroll
            for (int ks = 0; ks < 4; ks++) {
                const uint32_t xa = ((uint32_t)(ks * 32)) ^ xbaseA;
                const uint32_t xb = ((uint32_t)(ks * 32)) ^ xbaseB;
                uint32_t a[4][4], b[2][4];
                #pragma unroll
                for (int i = 0; i < 4; i++)
                    ldm_x4(a[i][0], a[i][1], a[i][2], a[i][3], aBase + i * 2048 + xa);
                #pragma unroll
                for (int j16 = 0; j16 < 2; j16++)
                    ldm_x4(b[j16][0], b[j16][1], b[j16][2], b[j16][3],
                           bBase + j16 * 2048 + xb);
                #pragma unroll
                for (int i = 0; i < 4; i++)
                    #pragma unroll
                    for (int j2 = 0; j2 < 4; j2++)
                        mma16816(acc[i][j2], a[i], &b[j2 >> 1][(j2 & 1) * 2]);
            }
        }

        if ((ci % 12) == 11) {
            // tile epilogue: stage scores then scan.
            // No pre-store sync needed: all warps passed sync(ci), which is
            // after the previous tile's scan in program order.
            const int t = ci / 12;
            const int n0 = pbase + t * 128;
            #pragma unroll
            for (int i = 0; i < 4; i++) {
                int row = wm * 64 + i * 16 + (lane >> 2);
                #pragma unroll
                for (int j2 = 0; j2 < 4; j2++) {
                    int col = wn * 32 + j2 * 8 + (lane & 3) * 2;
                    scores[row * SC_PITCH + col]           = acc[i][j2][0];
                    scores[row * SC_PITCH + col + 1]       = acc[i][j2][1];
                    scores[(row + 8) * SC_PITCH + col]     = acc[i][j2][2];
                    scores[(row + 8) * SC_PITCH + col + 1] = acc[i][j2][3];
                    acc[i][j2][0] = 0.f; acc[i][j2][1] = 0.f;
                    acc[i][j2][2] = 0.f; acc[i][j2][3] = 0.f;
                }
            }
            __syncthreads();
            {
                const int r    = tid & 127;
                const int half = tid >> 7;
                const int cbase = n0 + half * 64;
                int nv = NN - cbase;
                nv = nv < 0 ? 0 : (nv > 64 ? 64 : nv);
                const float* srow = scores + r * SC_PITCH + half * 64;
                int c2 = 0;
                for (; c2 + 4 <= nv; c2 += 4) {
                    float s0 = srow[c2], s1 = srow[c2+1], s2 = srow[c2+2], s3 = srow[c2+3];
                    float mx = fmaxf(fmaxf(s0, s1), fmaxf(s2, s3));
                    if (mx > mv) {
                        #pragma unroll
                        for (int u = 0; u < 4; u++) {
                            float s = (u == 0) ? s0 : (u == 1) ? s1 : (u == 2) ? s2 : s3;
                            if (s > mv) {
                                #pragma unroll
                                for (int q = 0; q < TK; q++)
                                    if (q == mp) { tvv[q] = s; tii[q] = cbase + c2 + u; }
                                mv = tvv[0]; mp = 0; int mi = tii[0];
                                #pragma unroll
                                for (int q = 1; q < TK; q++) {
                                    if (tvv[q] < mv || (tvv[q] == mv && tii[q] > mi)) {
                                        mv = tvv[q]; mp = q; mi = tii[q];
                                    }
                                }
                            }
                        }
                    }
                }
                for (; c2 < nv; c2++) {
                    float s = srow[c2];
                    if (s > mv) {
                        #pragma unroll
                        for (int q = 0; q < TK; q++)
                            if (q == mp) { tvv[q] = s; tii[q] = cbase + c2; }
                        mv = tvv[0]; mp = 0; int mi = tii[0];
                        #pragma unroll
                        for (int q = 1; q < TK; q++) {
                            if (tvv[q] < mv || (tvv[q] == mv && tii[q] > mi)) {
                                mv = tvv[q]; mp = q; mi = tii[q];
                            }
                        }
                    }
                }
            }
            // next iteration's top sync guarantees all scans done before the
            // scores region is rewritten 12 chunks later
        }
    }

    // dump candidate lists: list id = part*2 + half
    {
        const int b = m0 + (tid & 127);
        const int list = part * 2 + (tid >> 7);
        const size_t base = ((size_t)b * NLISTS + list) * TK;
        #pragma unroll
        for (int q = 0; q < TK; q++) { g_pvals[base + q] = tvv[q]; g_pidx[base + q] = tii[q]; }
    }
}

// ---------------------------------------------------------------------------
// Kernel 2: merge 74x16 partials -> top-32 candidate pool per row (warp/row)
// ---------------------------------------------------------------------------
__global__ void merge_kernel() {
    const int warp = threadIdx.x >> 5;
    const int lane = threadIdx.x & 31;
    const int row  = blockIdx.x * 8 + warp;
    if (row >= BB) return;

    const int NC = NLISTS * TK;   // 1184
    const int T = NC / 32;        // 37
    float lv[T]; int li[T];
    #pragma unroll
    for (int t = 0; t < T; t++) {
        int g = lane + t * 32;
        lv[t] = g_pvals[(size_t)row * NC + g];
        li[t] = g_pidx [(size_t)row * NC + g];
    }
    for (int rnd = 0; rnd < NCAND; rnd++) {
        float bv = NEG_INF; int bi = 0x7fffffff; int bs = -1;
        #pragma unroll
        for (int t = 0; t < T; t++)
            if (lv[t] > bv || (lv[t] == bv && li[t] < bi)) { bv = lv[t]; bi = li[t]; bs = t; }
        float wv = bv; int wi = bi;
        #pragma unroll
        for (int o = 16; o; o >>= 1) {
            float ov = __shfl_xor_sync(0xffffffffu, wv, o);
            int   oi = __shfl_xor_sync(0xffffffffu, wi, o);
            if (ov > wv || (ov == wv && oi < wi)) { wv = ov; wi = oi; }
        }
        if (bs >= 0 && bv == wv && bi == wi) { lv[bs] = NEG_INF; li[bs] = 0x7fffffff; }
        if (lane == 0) g_cand[row * NCAND + rnd] = wi;
    }
}

// ---------------------------------------------------------------------------
// Kernel 2.5a: fp64 exact sims — one WARP per (row, candidate)
// ---------------------------------------------------------------------------
__global__ void refine_dot_kernel(const float* __restrict__ X, const float* __restrict__ E) {
    const int gw   = blockIdx.x * 8 + (threadIdx.x >> 5);
    const int lane = threadIdx.x & 31;
    const int row  = gw >> 5;
    const int slot = gw & 31;
    if (row >= BB) return;
    const int cand = g_cand[row * NCAND + slot];
    const float4* x4 = reinterpret_cast<const float4*>(X + (size_t)row  * CC);
    const float4* e4 = reinterpret_cast<const float4*>(E + (size_t)cand * CC);

    double dot = 0.0, e2 = 0.0;
    #pragma unroll
    for (int i = 0; i < 6; i++) {
        float4 xv = x4[lane + 32 * i];
        float4 ev = e4[lane + 32 * i];
        dot = fma((double)xv.x, (double)ev.x, dot);
        e2  = fma((double)ev.x, (double)ev.x, e2);
        dot = fma((double)xv.y, (double)ev.y, dot);
        e2  = fma((double)ev.y, (double)ev.y, e2);
        dot = fma((double)xv.z, (double)ev.z, dot);
        e2  = fma((double)ev.z, (double)ev.z, e2);
        dot = fma((double)xv.w, (double)ev.w, dot);
        e2  = fma((double)ev.w, (double)ev.w, e2);
    }
    #pragma unroll
    for (int o = 16; o; o >>= 1) {
        dot += __shfl_xor_sync(0xffffffffu, dot, o);
        e2  += __shfl_xor_sync(0xffffffffu, e2,  o);
    }
    if (lane == 0) g_csim[row * NCAND + slot] = dot / sqrt(e2);
}

// Kernel 2.5b: sorted top-16 of the 32 exact sims (warp per row)
__global__ void refine_select_kernel() {
    const int warp = threadIdx.x >> 5;
    const int lane = threadIdx.x & 31;
    const int row  = blockIdx.x * 8 + warp;
    if (row >= BB) return;

    double v = g_csim[row * NCAND + lane];
    int  idx = g_cand[row * NCAND + lane];
    for (int rnd = 0; rnd < TK; rnd++) {
        double wv = v; int wi = idx;
        #pragma unroll
        for (int o = 16; o; o >>= 1) {
            double ov = __shfl_xor_sync(0xffffffffu, wv, o);
            int    oi = __shfl_xor_sync(0xffffffffu, wi, o);
            if (ov > wv || (ov == wv && oi < wi)) { wv = ov; wi = oi; }
        }
        if (idx == wi) { v = -INFINITY; idx = 0x7fffffff; }
        if (lane == 0) g_fidx[row * TK + rnd] = wi;
    }
}

// ---------------------------------------------------------------------------
// Kernel 3: gather with reference's reshape(-1,B,C).transpose(1,0,2) scramble
// ---------------------------------------------------------------------------
__global__ void gather_kernel(const float* __restrict__ E, float* __restrict__ out) {
    const int bj = blockIdx.x;        // b*16 + j
    const int b = bj >> 4, j = bj & 15;
    const int src_row  = j * (BB / TK) + (b >> 4);
    const int src_slot = b & 15;
    const int src = g_fidx[src_row * TK + src_slot];
    const float4* s4 = reinterpret_cast<const float4*>(E + (size_t)src * CC);
    float4* d4 = reinterpret_cast<float4*>(out + (size_t)bj * CC);
    d4[threadIdx.x] = s4[threadIdx.x];
}

// ---------------------------------------------------------------------------
extern "C" void kernel_launch(void* const* d_in, const int* in_sizes, int n_in,
                              void* d_out, int out_size) {
    const float* X = (const float*)d_in[0];
    const float* E = (const float*)d_in[1];
    float* out = (float*)d_out;
    (void)in_sizes; (void)n_in; (void)out_size;

    cudaFuncSetAttribute(gemm_topk_kernel,
                         cudaFuncAttributeMaxDynamicSharedMemorySize, GSMEM);

    prepE_kernel<<<NPAD / 8, 256>>>(E);     // launch 1
    prepX_kernel<<<BB / 8, 256>>>(X);       // launch 2
    dummy_kernel<<<1, 32>>>();              // launch 3 (so gemm is 4th -> profiled)
    gemm_topk_kernel<<<dim3(16, NPARTS), 256, GSMEM>>>();   // launch 4
    merge_kernel<<<BB / 8, 256>>>();
    refine_dot_kernel<<<BB * NCAND / 8, 256>>>(X, E);
    refine_select_kernel<<<BB / 8, 256>>>();
    gather_kernel<<<BB * TK, 192>>>(E, out);
}

// round 9
// speedup vs baseline: 2.2829x; 1.2717x over previous
#include <cuda_runtime.h>
#include <cuda_bf16.h>
#include <cstdint>
#include <math.h>

// ---------------------------------------------------------------------------
// Problem constants
#define BB 2048
#define NN 50000
#define CC 768
#define TK 16
#define NCAND 32
#define NPARTS 37
#define NT 11                 // 128-col tiles per part
#define PSPAN (NT*128)        // 1408
#define NPAD (NPARTS*PSPAN)   // 52096
#define NLISTS (2*NPARTS)     // 74 partial lists per row (2 col-halves per part)
#define NEG_INF __int_as_float(0xff800000)

// Scratch (device globals: no cudaMalloc allowed)
__device__ __nv_bfloat16 g_Ebf[(size_t)NPAD * CC];   // row-scaled by 1/||e||
__device__ __nv_bfloat16 g_Xbf[(size_t)BB * CC];
__device__ float  g_pvals[(size_t)BB * NLISTS * TK];
__device__ int    g_pidx [(size_t)BB * NLISTS * TK];
__device__ int    g_cand [(size_t)BB * NCAND];
__device__ double g_csim [(size_t)BB * NCAND];
__device__ int    g_fidx [(size_t)BB * TK];

// ---------------------------------------------------------------------------
// Baseline-PTX helpers (NO sm_103a-gated instructions)
// ---------------------------------------------------------------------------
__device__ __forceinline__ uint32_t smem_u32(const void* p) {
    uint32_t a;
    asm("{ .reg .u64 t; cvta.to.shared.u64 t, %1; cvt.u32.u64 %0, t; }" : "=r"(a) : "l"(p));
    return a;
}
__device__ __forceinline__ void cp16(uint32_t saddr, const void* g) {
    asm volatile("cp.async.cg.shared.global [%0], [%1], 16;" :: "r"(saddr), "l"(g));
}
#define CP_COMMIT() asm volatile("cp.async.commit_group;" ::: "memory")
#define CP_WAIT0()  asm volatile("cp.async.wait_group 0;" ::: "memory")

__device__ __forceinline__ void ldm_x4(uint32_t& r0, uint32_t& r1, uint32_t& r2,
                                       uint32_t& r3, uint32_t a) {
    asm volatile("ldmatrix.sync.aligned.m8n8.x4.shared.b16 {%0,%1,%2,%3}, [%4];"
                 : "=r"(r0), "=r"(r1), "=r"(r2), "=r"(r3) : "r"(a));
}
__device__ __forceinline__ void mma16816(float* c, const uint32_t* a, const uint32_t* b) {
    asm volatile(
        "mma.sync.aligned.m16n8k16.row.col.f32.bf16.bf16.f32 "
        "{%0,%1,%2,%3}, {%4,%5,%6,%7}, {%8,%9}, {%0,%1,%2,%3};"
        : "+f"(c[0]), "+f"(c[1]), "+f"(c[2]), "+f"(c[3])
        : "r"(a[0]), "r"(a[1]), "r"(a[2]), "r"(a[3]), "r"(b[0]), "r"(b[1]));
}
__device__ __forceinline__ uint32_t swz(uint32_t off) { return off ^ ((off >> 3) & 0x70); }

// ---------------------------------------------------------------------------
// Prepass: E -> bf16 scaled by 1/||e|| (rows >= NN zeroed); X -> bf16
// ---------------------------------------------------------------------------
__global__ void prepE_kernel(const float* __restrict__ E) {
    int w = (blockIdx.x * blockDim.x + threadIdx.x) >> 5;
    int lane = threadIdx.x & 31;
    if (w >= NPAD) return;
    uint32_t* orow = reinterpret_cast<uint32_t*>(g_Ebf + (size_t)w * CC);
    if (w >= NN) {
        #pragma unroll
        for (int i = 0; i < 6; i++) { orow[(lane+32*i)*2] = 0u; orow[(lane+32*i)*2+1] = 0u; }
        return;
    }
    const float4* r4 = reinterpret_cast<const float4*>(E + (size_t)w * CC);
    float s = 0.f;
    float4 v[6];
    #pragma unroll
    for (int i = 0; i < 6; i++) {
        v[i] = r4[lane + 32*i];
        s += v[i].x*v[i].x + v[i].y*v[i].y + v[i].z*v[i].z + v[i].w*v[i].w;
    }
    #pragma unroll
    for (int o = 16; o; o >>= 1) s += __shfl_xor_sync(0xffffffffu, s, o);
    float inv = rsqrtf(s);
    #pragma unroll
    for (int i = 0; i < 6; i++) {
        __nv_bfloat162 h0 = __floats2bfloat162_rn(v[i].x*inv, v[i].y*inv);
        __nv_bfloat162 h1 = __floats2bfloat162_rn(v[i].z*inv, v[i].w*inv);
        orow[(lane+32*i)*2]   = *reinterpret_cast<uint32_t*>(&h0);
        orow[(lane+32*i)*2+1] = *reinterpret_cast<uint32_t*>(&h1);
    }
}

__global__ void prepX_kernel(const float* __restrict__ X) {
    int w = (blockIdx.x * blockDim.x + threadIdx.x) >> 5;
    int lane = threadIdx.x & 31;
    if (w >= BB) return;
    const float4* r4 = reinterpret_cast<const float4*>(X + (size_t)w * CC);
    uint32_t* orow = reinterpret_cast<uint32_t*>(g_Xbf + (size_t)w * CC);
    #pragma unroll
    for (int i = 0; i < 6; i++) {
        float4 v = r4[lane + 32*i];
        __nv_bfloat162 h0 = __floats2bfloat162_rn(v.x, v.y);
        __nv_bfloat162 h1 = __floats2bfloat162_rn(v.z, v.w);
        orow[(lane+32*i)*2]   = *reinterpret_cast<uint32_t*>(&h0);
        orow[(lane+32*i)*2+1] = *reinterpret_cast<uint32_t*>(&h1);
    }
}

// Dummy no-op: placed as 3rd launch so ncu (which captures the 4th launch)
// profiles the GEMM kernel.
__global__ void dummy_kernel() {}

// ---------------------------------------------------------------------------
// Kernel 1: bf16 HMMA GEMM (mma.sync m16n8k16) + streaming per-row top-16.
// 128x128 CTA tile, 8 warps (2M x 4N), warp tile 64x32, K-chunk 64.
// 2-stage cp.async ring, ONE syncthreads per chunk, bf16 score staging.
// __launch_bounds__(256,2): 2 CTAs/SM for barrier-latency overlap.
// grid(16 Mblk, 37 parts), 256 threads.
// ---------------------------------------------------------------------------
#define NSTAGE      2
#define STAGE_BYTES 32768              // A 16KB + B 16KB
#define SC_OFF      (NSTAGE*STAGE_BYTES)   // 65536
#define SC_PITCH    132                // bf16 elements; 264B rows (8B aligned)
#define GSMEM       (SC_OFF + 128*SC_PITCH*2)   // 99,328 B -> 2 CTAs/SM

__global__ void __launch_bounds__(256, 2) gemm_topk_kernel() {
    extern __shared__ char sm[];
    const uint32_t smb = smem_u32(sm);
    __nv_bfloat16* scores = reinterpret_cast<__nv_bfloat16*>(sm + SC_OFF);

    const int tid  = threadIdx.x;
    const int warp = tid >> 5;
    const int lane = tid & 31;
    const int m0   = blockIdx.x * 128;
    const int part = blockIdx.y;
    const int pbase = part * PSPAN;

    const int wm = warp & 1;        // 2 M-warps (64 rows each)
    const int wn = warp >> 1;       // 4 N-warps (32 cols each)

    const int NCHUNK = NT * 12;     // 132

    // ---- hoisted cp.async per-thread address components
    const int cp_seg = tid & 7;
    uint32_t cp_sw[4];
    uint32_t cp_el[4];
    #pragma unroll
    for (int s = 0; s < 4; s++) {
        int row = (tid >> 3) + 32 * s;
        cp_sw[s] = (uint32_t)row * 128 + ((uint32_t)(cp_seg * 16) ^ (((uint32_t)row & 7) << 4));
        cp_el[s] = (uint32_t)row * CC + cp_seg * 8;
    }

    // ---- hoisted ldmatrix address components
    const int a_row = (lane & 15);
    const int a_kh  = (lane >> 4) & 1;
    const int b_nrw = ((lane >> 4) & 1) * 8 + (lane & 7);
    const int b_kh  = (lane >> 3) & 1;
    const uint32_t RA = (uint32_t)(wm * 64 + a_row) * 128;        // + i*2048
    const uint32_t RB = (uint32_t)(wn * 32 + b_nrw) * 128;        // + j16*2048
    const uint32_t xbaseA = ((uint32_t)(a_kh * 16)) ^ (((uint32_t)a_row & 7) << 4);
    const uint32_t xbaseB = ((uint32_t)(b_kh * 16)) ^ (((uint32_t)b_nrw & 7) << 4);

    // issue one 32KB stage (A chunk + B chunk) via cp.async; always commits
    auto issue = [&](int ci) {
        if (ci < NCHUNK) {
            const int t = ci / 12, c = ci - t * 12;
            const uint32_t as = smb + (ci & 1) * STAGE_BYTES;
            const uint32_t bs = as + 16384;
            const __nv_bfloat16* Ab = g_Xbf + (size_t)m0 * CC + c * 64;
            const __nv_bfloat16* Bb = g_Ebf + (size_t)(pbase + t * 128) * CC + c * 64;
            #pragma unroll
            for (int s = 0; s < 4; s++) {
                cp16(as + cp_sw[s], Ab + cp_el[s]);
                cp16(bs + cp_sw[s], Bb + cp_el[s]);
            }
        }
        CP_COMMIT();
    };

    // per-(row,half) streaming top-16 (thread tid: row=tid&127, half=tid>>7)
    float tvv[TK]; int tii[TK];
    #pragma unroll
    for (int q = 0; q < TK; q++) { tvv[q] = NEG_INF; tii[q] = 0x7fffffff; }
    float mv = NEG_INF; int mp = 0;

    float acc[4][4][4];
    #pragma unroll
    for (int i = 0; i < 4; i++)
        #pragma unroll
        for (int j = 0; j < 4; j++)
            #pragma unroll
            for (int r = 0; r < 4; r++) acc[i][j][r] = 0.f;

    issue(0);

    for (int ci = 0; ci < NCHUNK; ci++) {
        CP_WAIT0();          // all groups incl. ci complete
        __syncthreads();     // all warps done computing ci-1; data visible
        issue(ci + 1);       // into the stage of ci-1: safe after the barrier

        // compute chunk ci from stage ci & 1
        {
            const uint32_t as = smb + (ci & 1) * STAGE_BYTES;
            const uint32_t aBase = as + RA;
            const uint32_t bBase = as + 16384 + RB;
            #pragma unroll
            for (int ks = 0; ks < 4; ks++) {
                const uint32_t xa = ((uint32_t)(ks * 32)) ^ xbaseA;
                const uint32_t xb = ((uint32_t)(ks * 32)) ^ xbaseB;
                uint32_t a[4][4], b[2][4];
                #pragma unroll
                for (int i = 0; i < 4; i++)
                    ldm_x4(a[i][0], a[i][1], a[i][2], a[i][3], aBase + i * 2048 + xa);
                #pragma unroll
                for (int j16 = 0; j16 < 2; j16++)
                    ldm_x4(b[j16][0], b[j16][1], b[j16][2], b[j16][3],
                           bBase + j16 * 2048 + xb);
                #pragma unroll
                for (int i = 0; i < 4; i++)
                    #pragma unroll
                    for (int j2 = 0; j2 < 4; j2++)
                        mma16816(acc[i][j2], a[i], &b[j2 >> 1][(j2 & 1) * 2]);
            }
        }

        if ((ci % 12) == 11) {
            // tile epilogue: stage scores (bf16, packed pair stores) then scan
            const int t = ci / 12;
            const int n0 = pbase + t * 128;
            #pragma unroll
            for (int i = 0; i < 4; i++) {
                int row = wm * 64 + i * 16 + (lane >> 2);
                #pragma unroll
                for (int j2 = 0; j2 < 4; j2++) {
                    int col = wn * 32 + j2 * 8 + (lane & 3) * 2;
                    __nv_bfloat162 p0 = __floats2bfloat162_rn(acc[i][j2][0], acc[i][j2][1]);
                    __nv_bfloat162 p1 = __floats2bfloat162_rn(acc[i][j2][2], acc[i][j2][3]);
                    *reinterpret_cast<__nv_bfloat162*>(&scores[row * SC_PITCH + col]) = p0;
                    *reinterpret_cast<__nv_bfloat162*>(&scores[(row + 8) * SC_PITCH + col]) = p1;
                    acc[i][j2][0] = 0.f; acc[i][j2][1] = 0.f;
                    acc[i][j2][2] = 0.f; acc[i][j2][3] = 0.f;
                }
            }
            __syncthreads();
            {
                const int r    = tid & 127;
                const int half = tid >> 7;
                const int cbase = n0 + half * 64;
                int nv = NN - cbase;
                nv = nv < 0 ? 0 : (nv > 64 ? 64 : nv);
                const __nv_bfloat162* srow = reinterpret_cast<const __nv_bfloat162*>(
                    scores + r * SC_PITCH + half * 64);
                int c2 = 0;
                for (; c2 + 4 <= nv; c2 += 4) {
                    float2 f0 = __bfloat1622float2(srow[c2 >> 1]);
                    float2 f1 = __bfloat1622float2(srow[(c2 >> 1) + 1]);
                    float mx = fmaxf(fmaxf(f0.x, f0.y), fmaxf(f1.x, f1.y));
                    if (mx > mv) {
                        #pragma unroll
                        for (int u = 0; u < 4; u++) {
                            float s = (u == 0) ? f0.x : (u == 1) ? f0.y : (u == 2) ? f1.x : f1.y;
                            if (s > mv) {
                                #pragma unroll
                                for (int q = 0; q < TK; q++)
                                    if (q == mp) { tvv[q] = s; tii[q] = cbase + c2 + u; }
                                mv = tvv[0]; mp = 0; int mi = tii[0];
                                #pragma unroll
                                for (int q = 1; q < TK; q++) {
                                    if (tvv[q] < mv || (tvv[q] == mv && tii[q] > mi)) {
                                        mv = tvv[q]; mp = q; mi = tii[q];
                                    }
                                }
                            }
                        }
                    }
                }
                for (; c2 < nv; c2++) {
                    float s = __bfloat162float(scores[r * SC_PITCH + half * 64 + c2]);
                    if (s > mv) {
                        #pragma unroll
                        for (int q = 0; q < TK; q++)
                            if (q == mp) { tvv[q] = s; tii[q] = cbase + c2; }
                        mv = tvv[0]; mp = 0; int mi = tii[0];
                        #pragma unroll
                        for (int q = 1; q < TK; q++) {
                            if (tvv[q] < mv || (tvv[q] == mv && tii[q] > mi)) {
                                mv = tvv[q]; mp = q; mi = tii[q];
                            }
                        }
                    }
                }
            }
            // next iteration's top sync orders scans before score rewrites
        }
    }

    // dump candidate lists: list id = part*2 + half
    {
        const int b = m0 + (tid & 127);
        const int list = part * 2 + (tid >> 7);
        const size_t base = ((size_t)b * NLISTS + list) * TK;
        #pragma unroll
        for (int q = 0; q < TK; q++) { g_pvals[base + q] = tvv[q]; g_pidx[base + q] = tii[q]; }
    }
}

// ---------------------------------------------------------------------------
// Kernel 2: merge 74x16 partials -> top-32 candidate pool per row (warp/row)
// ---------------------------------------------------------------------------
__global__ void merge_kernel() {
    const int warp = threadIdx.x >> 5;
    const int lane = threadIdx.x & 31;
    const int row  = blockIdx.x * 8 + warp;
    if (row >= BB) return;

    const int NC = NLISTS * TK;   // 1184
    const int T = NC / 32;        // 37
    float lv[T]; int li[T];
    #pragma unroll
    for (int t = 0; t < T; t++) {
        int g = lane + t * 32;
        lv[t] = g_pvals[(size_t)row * NC + g];
        li[t] = g_pidx [(size_t)row * NC + g];
    }
    for (int rnd = 0; rnd < NCAND; rnd++) {
        float bv = NEG_INF; int bi = 0x7fffffff; int bs = -1;
        #pragma unroll
        for (int t = 0; t < T; t++)
            if (lv[t] > bv || (lv[t] == bv && li[t] < bi)) { bv = lv[t]; bi = li[t]; bs = t; }
        float wv = bv; int wi = bi;
        #pragma unroll
        for (int o = 16; o; o >>= 1) {
            float ov = __shfl_xor_sync(0xffffffffu, wv, o);
            int   oi = __shfl_xor_sync(0xffffffffu, wi, o);
            if (ov > wv || (ov == wv && oi < wi)) { wv = ov; wi = oi; }
        }
        if (bs >= 0 && bv == wv && bi == wi) { lv[bs] = NEG_INF; li[bs] = 0x7fffffff; }
        if (lane == 0) g_cand[row * NCAND + rnd] = wi;
    }
}

// ---------------------------------------------------------------------------
// Kernel 2.5a: fp64 exact sims — one WARP per (row, candidate)
// ---------------------------------------------------------------------------
__global__ void refine_dot_kernel(const float* __restrict__ X, const float* __restrict__ E) {
    const int gw   = blockIdx.x * 8 + (threadIdx.x >> 5);
    const int lane = threadIdx.x & 31;
    const int row  = gw >> 5;
    const int slot = gw & 31;
    if (row >= BB) return;
    const int cand = g_cand[row * NCAND + slot];
    const float4* x4 = reinterpret_cast<const float4*>(X + (size_t)row  * CC);
    const float4* e4 = reinterpret_cast<const float4*>(E + (size_t)cand * CC);

    double dot = 0.0, e2 = 0.0;
    #pragma unroll
    for (int i = 0; i < 6; i++) {
        float4 xv = x4[lane + 32 * i];
        float4 ev = e4[lane + 32 * i];
        dot = fma((double)xv.x, (double)ev.x, dot);
        e2  = fma((double)ev.x, (double)ev.x, e2);
        dot = fma((double)xv.y, (double)ev.y, dot);
        e2  = fma((double)ev.y, (double)ev.y, e2);
        dot = fma((double)xv.z, (double)ev.z, dot);
        e2  = fma((double)ev.z, (double)ev.z, e2);
        dot = fma((double)xv.w, (double)ev.w, dot);
        e2  = fma((double)ev.w, (double)ev.w, e2);
    }
    #pragma unroll
    for (int o = 16; o; o >>= 1) {
        dot += __shfl_xor_sync(0xffffffffu, dot, o);
        e2  += __shfl_xor_sync(0xffffffffu, e2,  o);
    }
    if (lane == 0) g_csim[row * NCAND + slot] = dot / sqrt(e2);
}

// Kernel 2.5b: sorted top-16 of the 32 exact sims (warp per row)
__global__ void refine_select_kernel() {
    const int warp = threadIdx.x >> 5;
    const int lane = threadIdx.x & 31;
    const int row  = blockIdx.x * 8 + warp;
    if (row >= BB) return;

    double v = g_csim[row * NCAND + lane];
    int  idx = g_cand[row * NCAND + lane];
    for (int rnd = 0; rnd < TK; rnd++) {
        double wv = v; int wi = idx;
        #pragma unroll
        for (int o = 16; o; o >>= 1) {
            double ov = __shfl_xor_sync(0xffffffffu, wv, o);
            int    oi = __shfl_xor_sync(0xffffffffu, wi, o);
            if (ov > wv || (ov == wv && oi < wi)) { wv = ov; wi = oi; }
        }
        if (idx == wi) { v = -INFINITY; idx = 0x7fffffff; }
        if (lane == 0) g_fidx[row * TK + rnd] = wi;
    }
}

// ---------------------------------------------------------------------------
// Kernel 3: gather with reference's reshape(-1,B,C).transpose(1,0,2) scramble
// ---------------------------------------------------------------------------
__global__ void gather_kernel(const float* __restrict__ E, float* __restrict__ out) {
    const int bj = blockIdx.x;        // b*16 + j
    const int b = bj >> 4, j = bj & 15;
    const int src_row  = j * (BB / TK) + (b >> 4);
    const int src_slot = b & 15;
    const int src = g_fidx[src_row * TK + src_slot];
    const float4* s4 = reinterpret_cast<const float4*>(E + (size_t)src * CC);
    float4* d4 = reinterpret_cast<float4*>(out + (size_t)bj * CC);
    d4[threadIdx.x] = s4[threadIdx.x];
}

// ---------------------------------------------------------------------------
extern "C" void kernel_launch(void* const* d_in, const int* in_sizes, int n_in,
                              void* d_out, int out_size) {
    const float* X = (const float*)d_in[0];
    const float* E = (const float*)d_in[1];
    float* out = (float*)d_out;
    (void)in_sizes; (void)n_in; (void)out_size;

    cudaFuncSetAttribute(gemm_topk_kernel,
                         cudaFuncAttributeMaxDynamicSharedMemorySize, GSMEM);

    prepE_kernel<<<NPAD / 8, 256>>>(E);     // launch 1
    prepX_kernel<<<BB / 8, 256>>>(X);       // launch 2
    dummy_kernel<<<1, 32>>>();              // launch 3 (so gemm is 4th -> profiled)
    gemm_topk_kernel<<<dim3(16, NPARTS), 256, GSMEM>>>();   // launch 4
    merge_kernel<<<BB / 8, 256>>>();
    refine_dot_kernel<<<BB * NCAND / 8, 256>>>(X, E);
    refine_select_kernel<<<BB / 8, 256>>>();
    gather_kernel<<<BB * TK, 192>>>(E, out);
}

// round 10
// speedup vs baseline: 2.3580x; 1.0329x over previous
#include <cuda_runtime.h>
#include <cuda_bf16.h>
#include <cstdint>
#include <math.h>

// ---------------------------------------------------------------------------
// Problem constants
#define BB 2048
#define NN 50000
#define CC 768
#define TK 16
#define NCAND 32
#define NPARTS 37
#define NT 11                 // 128-col tiles per part
#define PSPAN (NT*128)        // 1408
#define NPAD (NPARTS*PSPAN)   // 52096
#define NLISTS (2*NPARTS)     // 74 partial lists per row (2 col-halves per part)
#define NEG_INF __int_as_float(0xff800000)

// Scratch (device globals: no cudaMalloc allowed)
__device__ __nv_bfloat16 g_Ebf[(size_t)NPAD * CC];   // row-scaled by 1/||e||
__device__ __nv_bfloat16 g_Xbf[(size_t)BB * CC];
__device__ float  g_pvals[(size_t)BB * NLISTS * TK];
__device__ int    g_pidx [(size_t)BB * NLISTS * TK];
__device__ int    g_cand [(size_t)BB * NCAND];
__device__ double g_csim [(size_t)BB * NCAND];
__device__ int    g_fidx [(size_t)BB * TK];

// ---------------------------------------------------------------------------
// Baseline-PTX helpers (NO sm_103a-gated instructions)
// ---------------------------------------------------------------------------
__device__ __forceinline__ uint32_t smem_u32(const void* p) {
    uint32_t a;
    asm("{ .reg .u64 t; cvta.to.shared.u64 t, %1; cvt.u32.u64 %0, t; }" : "=r"(a) : "l"(p));
    return a;
}
__device__ __forceinline__ void cp16(uint32_t saddr, const void* g) {
    asm volatile("cp.async.cg.shared.global [%0], [%1], 16;" :: "r"(saddr), "l"(g));
}
#define CP_COMMIT() asm volatile("cp.async.commit_group;" ::: "memory")
#define CP_WAIT0()  asm volatile("cp.async.wait_group 0;" ::: "memory")

__device__ __forceinline__ void ldm_x4(uint32_t& r0, uint32_t& r1, uint32_t& r2,
                                       uint32_t& r3, uint32_t a) {
    asm volatile("ldmatrix.sync.aligned.m8n8.x4.shared.b16 {%0,%1,%2,%3}, [%4];"
                 : "=r"(r0), "=r"(r1), "=r"(r2), "=r"(r3) : "r"(a));
}
__device__ __forceinline__ void mma16816(float* c, const uint32_t* a, const uint32_t* b) {
    asm volatile(
        "mma.sync.aligned.m16n8k16.row.col.f32.bf16.bf16.f32 "
        "{%0,%1,%2,%3}, {%4,%5,%6,%7}, {%8,%9}, {%0,%1,%2,%3};"
        : "+f"(c[0]), "+f"(c[1]), "+f"(c[2]), "+f"(c[3])
        : "r"(a[0]), "r"(a[1]), "r"(a[2]), "r"(a[3]), "r"(b[0]), "r"(b[1]));
}

// ---------------------------------------------------------------------------
// Prepass: E -> bf16 scaled by 1/||e|| (rows >= NN zeroed); X -> bf16
// ---------------------------------------------------------------------------
__global__ void prepE_kernel(const float* __restrict__ E) {
    int w = (blockIdx.x * blockDim.x + threadIdx.x) >> 5;
    int lane = threadIdx.x & 31;
    if (w >= NPAD) return;
    uint32_t* orow = reinterpret_cast<uint32_t*>(g_Ebf + (size_t)w * CC);
    if (w >= NN) {
        #pragma unroll
        for (int i = 0; i < 6; i++) { orow[(lane+32*i)*2] = 0u; orow[(lane+32*i)*2+1] = 0u; }
        return;
    }
    const float4* r4 = reinterpret_cast<const float4*>(E + (size_t)w * CC);
    float s = 0.f;
    float4 v[6];
    #pragma unroll
    for (int i = 0; i < 6; i++) {
        v[i] = r4[lane + 32*i];
        s += v[i].x*v[i].x + v[i].y*v[i].y + v[i].z*v[i].z + v[i].w*v[i].w;
    }
    #pragma unroll
    for (int o = 16; o; o >>= 1) s += __shfl_xor_sync(0xffffffffu, s, o);
    float inv = rsqrtf(s);
    #pragma unroll
    for (int i = 0; i < 6; i++) {
        __nv_bfloat162 h0 = __floats2bfloat162_rn(v[i].x*inv, v[i].y*inv);
        __nv_bfloat162 h1 = __floats2bfloat162_rn(v[i].z*inv, v[i].w*inv);
        orow[(lane+32*i)*2]   = *reinterpret_cast<uint32_t*>(&h0);
        orow[(lane+32*i)*2+1] = *reinterpret_cast<uint32_t*>(&h1);
    }
}

__global__ void prepX_kernel(const float* __restrict__ X) {
    int w = (blockIdx.x * blockDim.x + threadIdx.x) >> 5;
    int lane = threadIdx.x & 31;
    if (w >= BB) return;
    const float4* r4 = reinterpret_cast<const float4*>(X + (size_t)w * CC);
    uint32_t* orow = reinterpret_cast<uint32_t*>(g_Xbf + (size_t)w * CC);
    #pragma unroll
    for (int i = 0; i < 6; i++) {
        float4 v = r4[lane + 32*i];
        __nv_bfloat162 h0 = __floats2bfloat162_rn(v.x, v.y);
        __nv_bfloat162 h1 = __floats2bfloat162_rn(v.z, v.w);
        orow[(lane+32*i)*2]   = *reinterpret_cast<uint32_t*>(&h0);
        orow[(lane+32*i)*2+1] = *reinterpret_cast<uint32_t*>(&h1);
    }
}

// Dummy no-op: placed as 3rd launch so ncu (which captures the 4th launch)
// profiles the GEMM kernel.
__global__ void dummy_kernel() {}

// ---------------------------------------------------------------------------
// Kernel 1: bf16 HMMA GEMM (mma.sync m16n8k16) + streaming per-row top-16.
// 128x128 CTA tile, 8 warps (2M x 4N), warp tile 64x32, K-chunk 64.
// 2-stage cp.async ring, ONE syncthreads per chunk, bf16 score staging.
// Fully-unrolled 12-chunk tile loop: all stage selects / offsets are
// compile-time immediates, killing the ALU address overhead.
// __launch_bounds__(256,2): 2 CTAs/SM. grid(16 Mblk, 37 parts), 256 thr.
// ---------------------------------------------------------------------------
#define NSTAGE      2
#define STAGE_BYTES 32768              // A 16KB + B 16KB
#define SC_OFF      (NSTAGE*STAGE_BYTES)   // 65536
#define SC_PITCH    132                // bf16 elements; 264B rows (8B aligned)
#define GSMEM       (SC_OFF + 128*SC_PITCH*2)   // 99,328 B -> 2 CTAs/SM

__global__ void __launch_bounds__(256, 2) gemm_topk_kernel() {
    extern __shared__ char sm[];
    const uint32_t smb = smem_u32(sm);
    __nv_bfloat16* scores = reinterpret_cast<__nv_bfloat16*>(sm + SC_OFF);

    const int tid  = threadIdx.x;
    const int warp = tid >> 5;
    const int lane = tid & 31;
    const int m0   = blockIdx.x * 128;
    const int part = blockIdx.y;
    const int pbase = part * PSPAN;

    const int wm = warp & 1;        // 2 M-warps (64 rows each)
    const int wn = warp >> 1;       // 4 N-warps (32 cols each)

    // ---- hoisted cp.async per-thread components
    const int cp_seg = tid & 7;
    uint32_t stA[4];                              // smem dst base (stage 0, A half)
    const __nv_bfloat16* pAe[4];                  // A global per-s pointer (fixed)
    const __nv_bfloat16* pBe[4];                  // B global per-s pointer (per tile)
    #pragma unroll
    for (int s = 0; s < 4; s++) {
        int row = (tid >> 3) + 32 * s;
        uint32_t sw = (uint32_t)row * 128 +
                      ((uint32_t)(cp_seg * 16) ^ (((uint32_t)row & 7) << 4));
        uint32_t el = (uint32_t)row * CC + cp_seg * 8;
        stA[s] = smb + sw;
        pAe[s] = g_Xbf + (size_t)m0 * CC + el;
        pBe[s] = g_Ebf + (size_t)pbase * CC + el;
    }

    // ---- hoisted ldmatrix components
    const int a_row = (lane & 15);
    const int a_kh  = (lane >> 4) & 1;
    const int b_nrw = ((lane >> 4) & 1) * 8 + (lane & 7);
    const int b_kh  = (lane >> 3) & 1;
    const uint32_t aB = smb + (uint32_t)(wm * 64 + a_row) * 128;           // + c&1 *32768
    const uint32_t bB = smb + 16384 + (uint32_t)(wn * 32 + b_nrw) * 128;
    uint32_t xaK[4], xbK[4];
    #pragma unroll
    for (int ks = 0; ks < 4; ks++) {
        xaK[ks] = ((uint32_t)(ks * 32)) ^ ((uint32_t)(a_kh * 16)) ^ (((uint32_t)a_row & 7) << 4);
        xbK[ks] = ((uint32_t)(ks * 32)) ^ ((uint32_t)(b_kh * 16)) ^ (((uint32_t)b_nrw & 7) << 4);
    }

    // per-(row,half) streaming top-16 (thread tid: row=tid&127, half=tid>>7)
    float tvv[TK]; int tii[TK];
    #pragma unroll
    for (int q = 0; q < TK; q++) { tvv[q] = NEG_INF; tii[q] = 0x7fffffff; }
    float mv = NEG_INF; int mp = 0;

    float acc[4][4][4];
    #pragma unroll
    for (int i = 0; i < 4; i++)
        #pragma unroll
        for (int j = 0; j < 4; j++)
            #pragma unroll
            for (int r = 0; r < 4; r++) acc[i][j][r] = 0.f;

    // prologue: issue chunk (t=0, c=0) into stage 0
    #pragma unroll
    for (int s = 0; s < 4; s++) {
        cp16(stA[s],         pAe[s]);
        cp16(stA[s] + 16384, pBe[s]);
    }
    CP_COMMIT();

    for (int t = 0; t < NT; t++) {
        #pragma unroll
        for (int c = 0; c < 12; c++) {
            CP_WAIT0();          // current chunk (t,c) resident
            __syncthreads();     // all warps done with previous chunk's stage
            // issue next chunk into the stage just freed (parity (c+1)&1)
            if (c < 11) {
                const uint32_t so = (uint32_t)(((c + 1) & 1) * 32768);
                #pragma unroll
                for (int s = 0; s < 4; s++) {
                    cp16(stA[s] + so,         pAe[s] + (c + 1) * 64);
                    cp16(stA[s] + so + 16384, pBe[s] + (c + 1) * 64);
                }
            } else if (t + 1 < NT) {
                #pragma unroll
                for (int s = 0; s < 4; s++) {
                    cp16(stA[s],         pAe[s]);
                    cp16(stA[s] + 16384, pBe[s] + 128 * CC);
                }
            }
            CP_COMMIT();

            // compute chunk (t,c) from stage c&1 (compile-time)
            const uint32_t so = (uint32_t)((c & 1) * 32768);
            #pragma unroll
            for (int ks = 0; ks < 4; ks++) {
                const uint32_t ax = aB + so + xaK[ks];
                const uint32_t bx = bB + so + xbK[ks];
                uint32_t a[4][4], b[2][4];
                #pragma unroll
                for (int i = 0; i < 4; i++)
                    ldm_x4(a[i][0], a[i][1], a[i][2], a[i][3], ax + i * 2048);
                #pragma unroll
                for (int j16 = 0; j16 < 2; j16++)
                    ldm_x4(b[j16][0], b[j16][1], b[j16][2], b[j16][3], bx + j16 * 2048);
                #pragma unroll
                for (int i = 0; i < 4; i++)
                    #pragma unroll
                    for (int j2 = 0; j2 < 4; j2++)
                        mma16816(acc[i][j2], a[i], &b[j2 >> 1][(j2 & 1) * 2]);
            }
        }

        // advance B tile pointers
        #pragma unroll
        for (int s = 0; s < 4; s++) pBe[s] += 128 * CC;

        // ---- tile epilogue: stage scores (bf16) then scan
        {
            const int n0 = pbase + t * 128;
            #pragma unroll
            for (int i = 0; i < 4; i++) {
                int row = wm * 64 + i * 16 + (lane >> 2);
                #pragma unroll
                for (int j2 = 0; j2 < 4; j2++) {
                    int col = wn * 32 + j2 * 8 + (lane & 3) * 2;
                    __nv_bfloat162 p0 = __floats2bfloat162_rn(acc[i][j2][0], acc[i][j2][1]);
                    __nv_bfloat162 p1 = __floats2bfloat162_rn(acc[i][j2][2], acc[i][j2][3]);
                    *reinterpret_cast<__nv_bfloat162*>(&scores[row * SC_PITCH + col]) = p0;
                    *reinterpret_cast<__nv_bfloat162*>(&scores[(row + 8) * SC_PITCH + col]) = p1;
                    acc[i][j2][0] = 0.f; acc[i][j2][1] = 0.f;
                    acc[i][j2][2] = 0.f; acc[i][j2][3] = 0.f;
                }
            }
            __syncthreads();
            {
                const int r    = tid & 127;
                const int half = tid >> 7;
                const int cbase = n0 + half * 64;
                int nv = NN - cbase;
                nv = nv < 0 ? 0 : (nv > 64 ? 64 : nv);
                const __nv_bfloat162* srow = reinterpret_cast<const __nv_bfloat162*>(
                    scores + r * SC_PITCH + half * 64);
                int c2 = 0;
                for (; c2 + 4 <= nv; c2 += 4) {
                    float2 f0 = __bfloat1622float2(srow[c2 >> 1]);
                    float2 f1 = __bfloat1622float2(srow[(c2 >> 1) + 1]);
                    float mx = fmaxf(fmaxf(f0.x, f0.y), fmaxf(f1.x, f1.y));
                    if (mx > mv) {
                        #pragma unroll
                        for (int u = 0; u < 4; u++) {
                            float s = (u == 0) ? f0.x : (u == 1) ? f0.y : (u == 2) ? f1.x : f1.y;
                            if (s > mv) {
                                #pragma unroll
                                for (int q = 0; q < TK; q++)
                                    if (q == mp) { tvv[q] = s; tii[q] = cbase + c2 + u; }
                                mv = tvv[0]; mp = 0; int mi = tii[0];
                                #pragma unroll
                                for (int q = 1; q < TK; q++) {
                                    if (tvv[q] < mv || (tvv[q] == mv && tii[q] > mi)) {
                                        mv = tvv[q]; mp = q; mi = tii[q];
                                    }
                                }
                            }
                        }
                    }
                }
                for (; c2 < nv; c2++) {
                    float s = __bfloat162float(scores[r * SC_PITCH + half * 64 + c2]);
                    if (s > mv) {
                        #pragma unroll
                        for (int q = 0; q < TK; q++)
                            if (q == mp) { tvv[q] = s; tii[q] = cbase + c2; }
                        mv = tvv[0]; mp = 0; int mi = tii[0];
                        #pragma unroll
                        for (int q = 1; q < TK; q++) {
                            if (tvv[q] < mv || (tvv[q] == mv && tii[q] > mi)) {
                                mv = tvv[q]; mp = q; mi = tii[q];
                            }
                        }
                    }
                }
            }
            // next tile's first sync orders scans before score rewrites
        }
    }

    // dump candidate lists: list id = part*2 + half
    {
        const int b = m0 + (tid & 127);
        const int list = part * 2 + (tid >> 7);
        const size_t base = ((size_t)b * NLISTS + list) * TK;
        #pragma unroll
        for (int q = 0; q < TK; q++) { g_pvals[base + q] = tvv[q]; g_pidx[base + q] = tii[q]; }
    }
}

// ---------------------------------------------------------------------------
// Kernel 2: merge 74x16 partials -> top-32 candidate pool per row (warp/row)
// ---------------------------------------------------------------------------
__global__ void merge_kernel() {
    const int warp = threadIdx.x >> 5;
    const int lane = threadIdx.x & 31;
    const int row  = blockIdx.x * 8 + warp;
    if (row >= BB) return;

    const int NC = NLISTS * TK;   // 1184
    const int T = NC / 32;        // 37
    float lv[T]; int li[T];
    #pragma unroll
    for (int t = 0; t < T; t++) {
        int g = lane + t * 32;
        lv[t] = g_pvals[(size_t)row * NC + g];
        li[t] = g_pidx [(size_t)row * NC + g];
    }
    for (int rnd = 0; rnd < NCAND; rnd++) {
        float bv = NEG_INF; int bi = 0x7fffffff; int bs = -1;
        #pragma unroll
        for (int t = 0; t < T; t++)
            if (lv[t] > bv || (lv[t] == bv && li[t] < bi)) { bv = lv[t]; bi = li[t]; bs = t; }
        float wv = bv; int wi = bi;
        #pragma unroll
        for (int o = 16; o; o >>= 1) {
            float ov = __shfl_xor_sync(0xffffffffu, wv, o);
            int   oi = __shfl_xor_sync(0xffffffffu, wi, o);
            if (ov > wv || (ov == wv && oi < wi)) { wv = ov; wi = oi; }
        }
        if (bs >= 0 && bv == wv && bi == wi) { lv[bs] = NEG_INF; li[bs] = 0x7fffffff; }
        if (lane == 0) g_cand[row * NCAND + rnd] = wi;
    }
}

// ---------------------------------------------------------------------------
// Kernel 2.5a: fp64 exact sims — one WARP per (row, candidate)
// ---------------------------------------------------------------------------
__global__ void refine_dot_kernel(const float* __restrict__ X, const float* __restrict__ E) {
    const int gw   = blockIdx.x * 8 + (threadIdx.x >> 5);
    const int lane = threadIdx.x & 31;
    const int row  = gw >> 5;
    const int slot = gw & 31;
    if (row >= BB) return;
    const int cand = g_cand[row * NCAND + slot];
    const float4* x4 = reinterpret_cast<const float4*>(X + (size_t)row  * CC);
    const float4* e4 = reinterpret_cast<const float4*>(E + (size_t)cand * CC);

    double dot = 0.0, e2 = 0.0;
    #pragma unroll
    for (int i = 0; i < 6; i++) {
        float4 xv = x4[lane + 32 * i];
        float4 ev = e4[lane + 32 * i];
        dot = fma((double)xv.x, (double)ev.x, dot);
        e2  = fma((double)ev.x, (double)ev.x, e2);
        dot = fma((double)xv.y, (double)ev.y, dot);
        e2  = fma((double)ev.y, (double)ev.y, e2);
        dot = fma((double)xv.z, (double)ev.z, dot);
        e2  = fma((double)ev.z, (double)ev.z, e2);
        dot = fma((double)xv.w, (double)ev.w, dot);
        e2  = fma((double)ev.w, (double)ev.w, e2);
    }
    #pragma unroll
    for (int o = 16; o; o >>= 1) {
        dot += __shfl_xor_sync(0xffffffffu, dot, o);
        e2  += __shfl_xor_sync(0xffffffffu, e2,  o);
    }
    if (lane == 0) g_csim[row * NCAND + slot] = dot / sqrt(e2);
}

// Kernel 2.5b: sorted top-16 of the 32 exact sims (warp per row)
__global__ void refine_select_kernel() {
    const int warp = threadIdx.x >> 5;
    const int lane = threadIdx.x & 31;
    const int row  = blockIdx.x * 8 + warp;
    if (row >= BB) return;

    double v = g_csim[row * NCAND + lane];
    int  idx = g_cand[row * NCAND + lane];
    for (int rnd = 0; rnd < TK; rnd++) {
        double wv = v; int wi = idx;
        #pragma unroll
        for (int o = 16; o; o >>= 1) {
            double ov = __shfl_xor_sync(0xffffffffu, wv, o);
            int    oi = __shfl_xor_sync(0xffffffffu, wi, o);
            if (ov > wv || (ov == wv && oi < wi)) { wv = ov; wi = oi; }
        }
        if (idx == wi) { v = -INFINITY; idx = 0x7fffffff; }
        if (lane == 0) g_fidx[row * TK + rnd] = wi;
    }
}

// ---------------------------------------------------------------------------
// Kernel 3: gather with reference's reshape(-1,B,C).transpose(1,0,2) scramble
// ---------------------------------------------------------------------------
__global__ void gather_kernel(const float* __restrict__ E, float* __restrict__ out) {
    const int bj = blockIdx.x;        // b*16 + j
    const int b = bj >> 4, j = bj & 15;
    const int src_row  = j * (BB / TK) + (b >> 4);
    const int src_slot = b & 15;
    const int src = g_fidx[src_row * TK + src_slot];
    const float4* s4 = reinterpret_cast<const float4*>(E + (size_t)src * CC);
    float4* d4 = reinterpret_cast<float4*>(out + (size_t)bj * CC);
    d4[threadIdx.x] = s4[threadIdx.x];
}

// ---------------------------------------------------------------------------
extern "C" void kernel_launch(void* const* d_in, const int* in_sizes, int n_in,
                              void* d_out, int out_size) {
    const float* X = (const float*)d_in[0];
    const float* E = (const float*)d_in[1];
    float* out = (float*)d_out;
    (void)in_sizes; (void)n_in; (void)out_size;

    cudaFuncSetAttribute(gemm_topk_kernel,
                         cudaFuncAttributeMaxDynamicSharedMemorySize, GSMEM);

    prepE_kernel<<<NPAD / 8, 256>>>(E);     // launch 1
    prepX_kernel<<<BB / 8, 256>>>(X);       // launch 2
    dummy_kernel<<<1, 32>>>();              // launch 3 (so gemm is 4th -> profiled)
    gemm_topk_kernel<<<dim3(16, NPARTS), 256, GSMEM>>>();   // launch 4
    merge_kernel<<<BB / 8, 256>>>();
    refine_dot_kernel<<<BB * NCAND / 8, 256>>>(X, E);
    refine_select_kernel<<<BB / 8, 256>>>();
    gather_kernel<<<BB * TK, 192>>>(E, out);
}